// round 7
// baseline (speedup 1.0000x reference)
#include <cuda_runtime.h>
#include <cuda_bf16.h>
#include <cstdint>

// ---------------------------------------------------------------------------
// SlidingWindowTransformer: B=4,S=512,D=256,W=32,L=4,H=8,DH=32,DFF=1024,NOUT=32
// Round 7: GEMM v3 — warp tile 64x64 (4 warps, 128 threads, CTA 128x128).
// LDSM:MMA ratio 16:96 per k16 (was 12:48) => 33% less shared-pipe per tensor
// op, which R4 ncu showed to be the binding pipe (L1 87%, tensor 39%).
// Everything else (attn v2, producers emitting bf16 hi/lo) unchanged from R6.
// ---------------------------------------------------------------------------

namespace {
constexpr int Dm   = 256;
constexpr int DFF  = 1024;
constexpr int NWIN = 2048;            // B*S
constexpr int NTOK = NWIN * 32;       // 65536
constexpr float EPS   = 1e-5f;
constexpr float SCALE = 0.17677669529663687f;  // 32^-0.5
constexpr int GSMEM = 2 * 40960;      // 2 stages x (4 tiles x 10240B)
}

// fp32 scratch
__device__ float g_x  [(size_t)NTOK * Dm];     // activations (residual base)
__device__ float g_qkv[(size_t)NTOK * 768];    // QKV gemm output (fp32 for attn)
__device__ float g_tmp[(size_t)NTOK * Dm];     // o-proj / ffn2 fp32 outputs
// bf16 hi/lo activation scratch
__device__ __nv_bfloat16 g_xh[(size_t)NTOK * Dm];
__device__ __nv_bfloat16 g_xl[(size_t)NTOK * Dm];
__device__ __nv_bfloat16 g_ah[(size_t)NTOK * Dm];
__device__ __nv_bfloat16 g_al[(size_t)NTOK * Dm];
__device__ __nv_bfloat16 g_fh[(size_t)NTOK * DFF];
__device__ __nv_bfloat16 g_fl[(size_t)NTOK * DFF];
// bf16 hi/lo weights (pre-converted each replay; cheap + deterministic)
__device__ __nv_bfloat16 g_winh[4 * 768 * 256],  g_winl[4 * 768 * 256];
__device__ __nv_bfloat16 g_woh [4 * 256 * 256],  g_wol [4 * 256 * 256];
__device__ __nv_bfloat16 g_w1h [4 * 1024 * 256], g_w1l [4 * 1024 * 256];
__device__ __nv_bfloat16 g_w2h [4 * 256 * 1024], g_w2l [4 * 256 * 1024];

// ---------------------------------------------------------------------------
// helpers
// ---------------------------------------------------------------------------
__device__ __forceinline__ void ldsm4(uint32_t* r, uint32_t addr) {
    asm volatile("ldmatrix.sync.aligned.m8n8.x4.shared.b16 {%0,%1,%2,%3}, [%4];"
                 : "=r"(r[0]), "=r"(r[1]), "=r"(r[2]), "=r"(r[3]) : "r"(addr));
}
__device__ __forceinline__ void mma16816(float* c, const uint32_t* a,
                                         uint32_t b0, uint32_t b1) {
    asm volatile(
        "mma.sync.aligned.m16n8k16.row.col.f32.bf16.bf16.f32 "
        "{%0,%1,%2,%3}, {%4,%5,%6,%7}, {%8,%9}, {%0,%1,%2,%3};"
        : "+f"(c[0]), "+f"(c[1]), "+f"(c[2]), "+f"(c[3])
        : "r"(a[0]), "r"(a[1]), "r"(a[2]), "r"(a[3]), "r"(b0), "r"(b1));
}
__device__ __forceinline__ void cp_async16(uint32_t dst, const void* src) {
    asm volatile("cp.async.cg.shared.global [%0], [%1], 16;"
                 :: "r"(dst), "l"(src) : "memory");
}
__device__ __forceinline__ uint32_t pack2(__nv_bfloat16 a, __nv_bfloat16 b) {
    __nv_bfloat162 t{a, b};
    return *reinterpret_cast<uint32_t*>(&t);
}
__device__ __forceinline__ void split2(float x, float y,
                                       uint32_t& hi, uint32_t& lo) {
    __nv_bfloat16 hx = __float2bfloat16(x);
    __nv_bfloat16 hy = __float2bfloat16(y);
    __nv_bfloat16 lx = __float2bfloat16(x - __bfloat162float(hx));
    __nv_bfloat16 ly = __float2bfloat16(y - __bfloat162float(hy));
    hi = pack2(hx, hy);
    lo = pack2(lx, ly);
}

// ---------------------------------------------------------------------------
// Weight prep: fp32 -> bf16 hi/lo
// ---------------------------------------------------------------------------
__global__ void prep_kernel(const float* __restrict__ src,
                            __nv_bfloat16* __restrict__ dh,
                            __nv_bfloat16* __restrict__ dl, int n) {
    int i = blockIdx.x * 256 + threadIdx.x;
    if (i >= n) return;
    float v = src[i];
    __nv_bfloat16 h = __float2bfloat16(v);
    dh[i] = h;
    dl[i] = __float2bfloat16(v - __bfloat162float(h));
}

// ---------------------------------------------------------------------------
// GEMM v3 (NT): C[M,N] = (Ah+Al)[M,K] @ (Bh+Bl)[N,K]^T + bias[N]
// MODE 0: fp32 out.  MODE 3: ReLU then bf16 hi/lo out.
// CTA 128x128, BK=32, 4 warps (2Mx2N), warp tile 64x64, cp.async 2-stage.
// SMEM per stage: Ah@0, Al@10240, Bh@20480, Bl@30720 (rows padded to 80B).
// ---------------------------------------------------------------------------
template <int MODE>
__global__ void __launch_bounds__(128, 2) mma_gemm3(
    const __nv_bfloat16* __restrict__ Ah, const __nv_bfloat16* __restrict__ Al,
    const __nv_bfloat16* __restrict__ Bh, const __nv_bfloat16* __restrict__ Bl,
    const float* __restrict__ bias,
    float* __restrict__ C,
    __nv_bfloat16* __restrict__ Ch, __nv_bfloat16* __restrict__ Cl,
    int K, int N)
{
    extern __shared__ char smem[];
    const uint32_t sb0 = (uint32_t)__cvta_generic_to_shared(smem);

    const int tid  = threadIdx.x;
    const int lane = tid & 31;
    const int wid  = tid >> 5;
    const int bm   = blockIdx.y * 128;
    const int bn   = blockIdx.x * 128;
    const int m0   = (wid >> 1) * 64;
    const int n0   = (wid & 1) * 64;

    const int lrow = lane & 15;
    const int lch  = lane >> 4;
    uint32_t aOff[4], bOff[4];
#pragma unroll
    for (int i = 0; i < 4; i++) {
        aOff[i] = (uint32_t)((m0 + i * 16 + lrow) * 80 + lch * 16);
        bOff[i] = (uint32_t)((n0 + i * 16 + lrow) * 80 + lch * 16);
    }

    float c[4][8][4];
#pragma unroll
    for (int i = 0; i < 4; i++)
#pragma unroll
        for (int j = 0; j < 8; j++)
#pragma unroll
            for (int k = 0; k < 4; k++) c[i][j][k] = 0.f;

    auto load_stage = [&](int s, int k0) {
        uint32_t base = sb0 + s * 40960;
#pragma unroll
        for (int i = 0; i < 4; i++) {
            int cc  = tid + i * 128;        // chunk id 0..511
            int row = cc >> 2;
            int kc  = cc & 3;
            uint32_t d = base + (uint32_t)(row * 80 + kc * 16);
            size_t ao = (size_t)(bm + row) * K + k0 + kc * 8;
            size_t bo = (size_t)(bn + row) * K + k0 + kc * 8;
            cp_async16(d,         Ah + ao);
            cp_async16(d + 10240, Al + ao);
            cp_async16(d + 20480, Bh + bo);
            cp_async16(d + 30720, Bl + bo);
        }
        asm volatile("cp.async.commit_group;" ::: "memory");
    };

    load_stage(0, 0);
    const int ntile = K >> 5;
    for (int it = 0; it < ntile; it++) {
        if (it + 1 < ntile) {
            load_stage((it + 1) & 1, (it + 1) * 32);
            asm volatile("cp.async.wait_group 1;" ::: "memory");
        } else {
            asm volatile("cp.async.wait_group 0;" ::: "memory");
        }
        __syncthreads();

        uint32_t base = sb0 + (it & 1) * 40960;
#pragma unroll
        for (int ks = 0; ks < 2; ks++) {
            const uint32_t ko = ks * 32;
            uint32_t a[16], bh[16], bl[16];
            ldsm4(a + 0,  base + aOff[0] + ko);
            ldsm4(a + 4,  base + aOff[1] + ko);
            ldsm4(a + 8,  base + aOff[2] + ko);
            ldsm4(a + 12, base + aOff[3] + ko);
            ldsm4(bh + 0,  base + 20480 + bOff[0] + ko);
            ldsm4(bh + 4,  base + 20480 + bOff[1] + ko);
            ldsm4(bh + 8,  base + 20480 + bOff[2] + ko);
            ldsm4(bh + 12, base + 20480 + bOff[3] + ko);
            ldsm4(bl + 0,  base + 30720 + bOff[0] + ko);
            ldsm4(bl + 4,  base + 30720 + bOff[1] + ko);
            ldsm4(bl + 8,  base + 30720 + bOff[2] + ko);
            ldsm4(bl + 12, base + 30720 + bOff[3] + ko);
            // A_hi * (B_hi + B_lo)
#pragma unroll
            for (int mi = 0; mi < 4; mi++)
#pragma unroll
                for (int j = 0; j < 8; j++) {
                    int g4 = (j >> 1) * 4, jj = j & 1;
                    mma16816(c[mi][j], a + mi * 4, bh[g4 + jj], bh[g4 + 2 + jj]);
                    mma16816(c[mi][j], a + mi * 4, bl[g4 + jj], bl[g4 + 2 + jj]);
                }
            // A_lo * B_hi
            ldsm4(a + 0,  base + 10240 + aOff[0] + ko);
            ldsm4(a + 4,  base + 10240 + aOff[1] + ko);
            ldsm4(a + 8,  base + 10240 + aOff[2] + ko);
            ldsm4(a + 12, base + 10240 + aOff[3] + ko);
#pragma unroll
            for (int mi = 0; mi < 4; mi++)
#pragma unroll
                for (int j = 0; j < 8; j++) {
                    int g4 = (j >> 1) * 4, jj = j & 1;
                    mma16816(c[mi][j], a + mi * 4, bh[g4 + jj], bh[g4 + 2 + jj]);
                }
        }
        __syncthreads();
    }

    // epilogue
    const int g  = lane >> 2;
    const int t2 = lane & 3;
#pragma unroll
    for (int mi = 0; mi < 4; mi++) {
        int r0 = bm + m0 + mi * 16 + g;
#pragma unroll
        for (int j = 0; j < 8; j++) {
            int col = bn + n0 + j * 8 + t2 * 2;
            float2 bv = *reinterpret_cast<const float2*>(&bias[col]);
            float v0x = c[mi][j][0] + bv.x, v0y = c[mi][j][1] + bv.y;
            float v1x = c[mi][j][2] + bv.x, v1y = c[mi][j][3] + bv.y;
            if (MODE == 0) {
                *reinterpret_cast<float2*>(&C[(size_t)r0 * N + col]) =
                    make_float2(v0x, v0y);
                *reinterpret_cast<float2*>(&C[(size_t)(r0 + 8) * N + col]) =
                    make_float2(v1x, v1y);
            } else {
                v0x = fmaxf(v0x, 0.f); v0y = fmaxf(v0y, 0.f);
                v1x = fmaxf(v1x, 0.f); v1y = fmaxf(v1y, 0.f);
                uint32_t h0, l0, h1, l1;
                split2(v0x, v0y, h0, l0);
                split2(v1x, v1y, h1, l1);
                *reinterpret_cast<uint32_t*>(&Ch[(size_t)r0 * N + col])       = h0;
                *reinterpret_cast<uint32_t*>(&Cl[(size_t)r0 * N + col])       = l0;
                *reinterpret_cast<uint32_t*>(&Ch[(size_t)(r0 + 8) * N + col]) = h1;
                *reinterpret_cast<uint32_t*>(&Cl[(size_t)(r0 + 8) * N + col]) = l1;
            }
        }
    }
}

// ---------------------------------------------------------------------------
// Gather: g_x fp32 + hi/lo copies
// ---------------------------------------------------------------------------
__global__ void gather_kernel(const float* __restrict__ X,
                              const float* __restrict__ pos) {
    int idx = blockIdx.x * 256 + threadIdx.x;  // float4 index over NTOK*64
    int d4 = idx & 63;
    int w  = (idx >> 6) & 31;
    int n  = idx >> 11;
    int s  = n & 511;
    int b  = n >> 9;
    int src = s - w; if (src < 0) src = 0;
    float4 xv = reinterpret_cast<const float4*>(X)[(size_t)(b * 512 + src) * 64 + d4];
    float4 pv = reinterpret_cast<const float4*>(pos)[(size_t)w * 64 + d4];
    float4 o  = make_float4(xv.x + pv.x, xv.y + pv.y, xv.z + pv.z, xv.w + pv.w);
    reinterpret_cast<float4*>(g_x)[idx] = o;
    uint32_t h0, l0, h1, l1;
    split2(o.x, o.y, h0, l0);
    split2(o.z, o.w, h1, l1);
    *reinterpret_cast<uint2*>(&g_xh[(size_t)idx * 4]) = make_uint2(h0, h1);
    *reinterpret_cast<uint2*>(&g_xl[(size_t)idx * 4]) = make_uint2(l0, l1);
}

// ---------------------------------------------------------------------------
// Attention v2: block = (window, head), 128 threads.
// ---------------------------------------------------------------------------
__global__ void attn_kernel2(const float* __restrict__ qkv,
                             __nv_bfloat16* __restrict__ oh,
                             __nv_bfloat16* __restrict__ ol) {
    __shared__ float qs[32][36];
    __shared__ float kT[32][36];   // kT[d][token]
    __shared__ float vs[32][36];
    __shared__ float ps[32][36];

    const int n   = blockIdx.x >> 3;
    const int h   = blockIdx.x & 7;
    const int tid = threadIdx.x;
    const int bse = n * 32;
    const int hc  = h * 32;

    for (int idx = tid; idx < 768; idx += 128) {
        int r = idx >> 3, c4 = idx & 7;
        int sect = r >> 5, tok = r & 31;
        float4 v = *reinterpret_cast<const float4*>(
            qkv + (size_t)(bse + tok) * 768 + sect * 256 + hc + c4 * 4);
        if (sect == 0) {
            *reinterpret_cast<float4*>(&qs[tok][c4 * 4]) = v;
        } else if (sect == 1) {
            kT[c4 * 4 + 0][tok] = v.x; kT[c4 * 4 + 1][tok] = v.y;
            kT[c4 * 4 + 2][tok] = v.z; kT[c4 * 4 + 3][tok] = v.w;
        } else {
            *reinterpret_cast<float4*>(&vs[tok][c4 * 4]) = v;
        }
    }
    __syncthreads();

    const int i  = tid >> 2;
    const int jc = tid & 3;

    float q[32];
#pragma unroll
    for (int u = 0; u < 8; u++) {
        float4 t = *reinterpret_cast<const float4*>(&qs[i][u * 4]);
        q[u * 4 + 0] = t.x * SCALE; q[u * 4 + 1] = t.y * SCALE;
        q[u * 4 + 2] = t.z * SCALE; q[u * 4 + 3] = t.w * SCALE;
    }
    float acc[8];
#pragma unroll
    for (int u = 0; u < 8; u++) acc[u] = 0.f;
#pragma unroll
    for (int d = 0; d < 32; d++) {
        float4 k0 = *reinterpret_cast<const float4*>(&kT[d][jc * 8]);
        float4 k1 = *reinterpret_cast<const float4*>(&kT[d][jc * 8 + 4]);
        float qd = q[d];
        acc[0] = fmaf(qd, k0.x, acc[0]); acc[1] = fmaf(qd, k0.y, acc[1]);
        acc[2] = fmaf(qd, k0.z, acc[2]); acc[3] = fmaf(qd, k0.w, acc[3]);
        acc[4] = fmaf(qd, k1.x, acc[4]); acc[5] = fmaf(qd, k1.y, acc[5]);
        acc[6] = fmaf(qd, k1.z, acc[6]); acc[7] = fmaf(qd, k1.w, acc[7]);
    }
    float mx = acc[0];
#pragma unroll
    for (int u = 1; u < 8; u++) mx = fmaxf(mx, acc[u]);
    mx = fmaxf(mx, __shfl_xor_sync(0xffffffffu, mx, 1));
    mx = fmaxf(mx, __shfl_xor_sync(0xffffffffu, mx, 2));
    float sum = 0.f;
#pragma unroll
    for (int u = 0; u < 8; u++) { acc[u] = __expf(acc[u] - mx); sum += acc[u]; }
    sum += __shfl_xor_sync(0xffffffffu, sum, 1);
    sum += __shfl_xor_sync(0xffffffffu, sum, 2);
    float inv = 1.f / sum;
#pragma unroll
    for (int u = 0; u < 8; u++) acc[u] *= inv;
    *reinterpret_cast<float4*>(&ps[i][jc * 8]) =
        make_float4(acc[0], acc[1], acc[2], acc[3]);
    *reinterpret_cast<float4*>(&ps[i][jc * 8 + 4]) =
        make_float4(acc[4], acc[5], acc[6], acc[7]);
    __syncthreads();

    float o[8];
#pragma unroll
    for (int u = 0; u < 8; u++) o[u] = 0.f;
#pragma unroll
    for (int j = 0; j < 32; j++) {
        float pj = ps[i][j];
        float4 v0 = *reinterpret_cast<const float4*>(&vs[j][jc * 8]);
        float4 v1 = *reinterpret_cast<const float4*>(&vs[j][jc * 8 + 4]);
        o[0] = fmaf(pj, v0.x, o[0]); o[1] = fmaf(pj, v0.y, o[1]);
        o[2] = fmaf(pj, v0.z, o[2]); o[3] = fmaf(pj, v0.w, o[3]);
        o[4] = fmaf(pj, v1.x, o[4]); o[5] = fmaf(pj, v1.y, o[5]);
        o[6] = fmaf(pj, v1.z, o[6]); o[7] = fmaf(pj, v1.w, o[7]);
    }
    uint32_t hp[4], lp[4];
    split2(o[0], o[1], hp[0], lp[0]);
    split2(o[2], o[3], hp[1], lp[1]);
    split2(o[4], o[5], hp[2], lp[2]);
    split2(o[6], o[7], hp[3], lp[3]);
    size_t base = (size_t)(bse + i) * 256 + hc + jc * 8;
    *reinterpret_cast<uint4*>(&oh[base]) = make_uint4(hp[0], hp[1], hp[2], hp[3]);
    *reinterpret_cast<uint4*>(&ol[base]) = make_uint4(lp[0], lp[1], lp[2], lp[3]);
}

// ---------------------------------------------------------------------------
// Residual add + LayerNorm: updates g_x fp32 and writes hi/lo copies.
// ---------------------------------------------------------------------------
__global__ void add_ln_kernel(const float* __restrict__ y,
                              const float* __restrict__ gg,
                              const float* __restrict__ bb) {
    int warp  = threadIdx.x >> 5;
    int lane  = threadIdx.x & 31;
    int token = blockIdx.x * 8 + warp;
    int c0    = lane * 8;
    float* xr = g_x + (size_t)token * 256;
    const float* yr = y + (size_t)token * 256;

    float v[8];
    float4 x0 = *reinterpret_cast<const float4*>(xr + c0);
    float4 x1 = *reinterpret_cast<const float4*>(xr + c0 + 4);
    float4 y0 = *reinterpret_cast<const float4*>(yr + c0);
    float4 y1 = *reinterpret_cast<const float4*>(yr + c0 + 4);
    v[0] = x0.x + y0.x; v[1] = x0.y + y0.y; v[2] = x0.z + y0.z; v[3] = x0.w + y0.w;
    v[4] = x1.x + y1.x; v[5] = x1.y + y1.y; v[6] = x1.z + y1.z; v[7] = x1.w + y1.w;

    float s = 0.f;
#pragma unroll
    for (int j = 0; j < 8; j++) s += v[j];
#pragma unroll
    for (int o = 16; o > 0; o >>= 1) s += __shfl_xor_sync(0xffffffffu, s, o);
    float mu = s * (1.f / 256.f);
    float s2 = 0.f;
#pragma unroll
    for (int j = 0; j < 8; j++) { float d = v[j] - mu; s2 += d * d; }
#pragma unroll
    for (int o = 16; o > 0; o >>= 1) s2 += __shfl_xor_sync(0xffffffffu, s2, o);
    float rstd = rsqrtf(s2 * (1.f / 256.f) + EPS);

    float4 g0 = *reinterpret_cast<const float4*>(gg + c0);
    float4 g1 = *reinterpret_cast<const float4*>(gg + c0 + 4);
    float4 b0 = *reinterpret_cast<const float4*>(bb + c0);
    float4 b1 = *reinterpret_cast<const float4*>(bb + c0 + 4);
    float r[8];
    r[0] = (v[0] - mu) * rstd * g0.x + b0.x; r[1] = (v[1] - mu) * rstd * g0.y + b0.y;
    r[2] = (v[2] - mu) * rstd * g0.z + b0.z; r[3] = (v[3] - mu) * rstd * g0.w + b0.w;
    r[4] = (v[4] - mu) * rstd * g1.x + b1.x; r[5] = (v[5] - mu) * rstd * g1.y + b1.y;
    r[6] = (v[6] - mu) * rstd * g1.z + b1.z; r[7] = (v[7] - mu) * rstd * g1.w + b1.w;

    *reinterpret_cast<float4*>(xr + c0)     = make_float4(r[0], r[1], r[2], r[3]);
    *reinterpret_cast<float4*>(xr + c0 + 4) = make_float4(r[4], r[5], r[6], r[7]);
    uint32_t hp[4], lp[4];
    split2(r[0], r[1], hp[0], lp[0]);
    split2(r[2], r[3], hp[1], lp[1]);
    split2(r[4], r[5], hp[2], lp[2]);
    split2(r[6], r[7], hp[3], lp[3]);
    size_t base = (size_t)token * 256 + c0;
    *reinterpret_cast<uint4*>(&g_xh[base]) = make_uint4(hp[0], hp[1], hp[2], hp[3]);
    *reinterpret_cast<uint4*>(&g_xl[base]) = make_uint4(lp[0], lp[1], lp[2], lp[3]);
}

// ---------------------------------------------------------------------------
// Head
// ---------------------------------------------------------------------------
__global__ void head_kernel(const float* __restrict__ hw,
                            const float* __restrict__ hb,
                            float* __restrict__ out) {
    __shared__ float hws[32][257];
    __shared__ float xs[8][256];
    int tid = threadIdx.x;
    for (int idx = tid; idx < 32 * 256; idx += 256) {
        int c = idx >> 8, d = idx & 255;
        hws[c][d] = hw[idx];
    }
    int warp = tid >> 5, lane = tid & 31;
    int n = blockIdx.x * 8 + warp;
    const float* xr = g_x + (size_t)(n * 32 + 31) * 256;
#pragma unroll
    for (int j = 0; j < 8; j++) xs[warp][lane + j * 32] = xr[lane + j * 32];
    __syncthreads();

    float accum = hb[lane];
#pragma unroll 8
    for (int d = 0; d < 256; d++) accum = fmaf(xs[warp][d], hws[lane][d], accum);
    out[(size_t)n * 32 + lane] = accum;
}

// ---------------------------------------------------------------------------
// Launch
// ---------------------------------------------------------------------------
extern "C" void kernel_launch(void* const* d_in, const int* in_sizes, int n_in,
                              void* d_out, int out_size) {
    const float* X    = (const float*)d_in[0];
    const float* pos  = (const float*)d_in[3];
    const float* w_in = (const float*)d_in[4];
    const float* b_in = (const float*)d_in[5];
    const float* w_o  = (const float*)d_in[6];
    const float* b_o  = (const float*)d_in[7];
    const float* w1   = (const float*)d_in[8];
    const float* b1   = (const float*)d_in[9];
    const float* w2   = (const float*)d_in[10];
    const float* b2   = (const float*)d_in[11];
    const float* l1g  = (const float*)d_in[12];
    const float* l1b  = (const float*)d_in[13];
    const float* l2g  = (const float*)d_in[14];
    const float* l2b  = (const float*)d_in[15];
    const float* hw   = (const float*)d_in[16];
    const float* hb   = (const float*)d_in[17];
    float* out = (float*)d_out;

    void* p;
    typedef __nv_bfloat16 bf;
    cudaGetSymbolAddress(&p, g_qkv);  float* qkv = (float*)p;
    cudaGetSymbolAddress(&p, g_tmp);  float* tmp = (float*)p;
    cudaGetSymbolAddress(&p, g_xh);   bf* xh = (bf*)p;
    cudaGetSymbolAddress(&p, g_xl);   bf* xl = (bf*)p;
    cudaGetSymbolAddress(&p, g_ah);   bf* ah = (bf*)p;
    cudaGetSymbolAddress(&p, g_al);   bf* al = (bf*)p;
    cudaGetSymbolAddress(&p, g_fh);   bf* fh = (bf*)p;
    cudaGetSymbolAddress(&p, g_fl);   bf* fl = (bf*)p;
    cudaGetSymbolAddress(&p, g_winh); bf* winh = (bf*)p;
    cudaGetSymbolAddress(&p, g_winl); bf* winl = (bf*)p;
    cudaGetSymbolAddress(&p, g_woh);  bf* woh = (bf*)p;
    cudaGetSymbolAddress(&p, g_wol);  bf* wol = (bf*)p;
    cudaGetSymbolAddress(&p, g_w1h);  bf* w1h = (bf*)p;
    cudaGetSymbolAddress(&p, g_w1l);  bf* w1l = (bf*)p;
    cudaGetSymbolAddress(&p, g_w2h);  bf* w2h = (bf*)p;
    cudaGetSymbolAddress(&p, g_w2l);  bf* w2l = (bf*)p;

    cudaFuncSetAttribute(mma_gemm3<0>,
        cudaFuncAttributeMaxDynamicSharedMemorySize, GSMEM);
    cudaFuncSetAttribute(mma_gemm3<3>,
        cudaFuncAttributeMaxDynamicSharedMemorySize, GSMEM);

    prep_kernel<<<(4 * 768 * 256 + 255) / 256, 256>>>(w_in, winh, winl, 4 * 768 * 256);
    prep_kernel<<<(4 * 256 * 256 + 255) / 256, 256>>>(w_o, woh, wol, 4 * 256 * 256);
    prep_kernel<<<(4 * 1024 * 256 + 255) / 256, 256>>>(w1, w1h, w1l, 4 * 1024 * 256);
    prep_kernel<<<(4 * 256 * 1024 + 255) / 256, 256>>>(w2, w2h, w2l, 4 * 256 * 1024);

    gather_kernel<<<NTOK * 64 / 256, 256>>>(X, pos);

    for (int l = 0; l < 4; l++) {
        // QKV: (65536 x 768), K=256, fp32 out for attn
        mma_gemm3<0><<<dim3(6, 512), 128, GSMEM>>>(
            xh, xl, winh + (size_t)l * 768 * 256, winl + (size_t)l * 768 * 256,
            b_in + (size_t)l * 768, qkv, nullptr, nullptr, 256, 768);
        attn_kernel2<<<NWIN * 8, 128>>>(qkv, ah, al);
        // o-proj: (65536 x 256), K=256, fp32 out
        mma_gemm3<0><<<dim3(2, 512), 128, GSMEM>>>(
            ah, al, woh + (size_t)l * 256 * 256, wol + (size_t)l * 256 * 256,
            b_o + (size_t)l * 256, tmp, nullptr, nullptr, 256, 256);
        add_ln_kernel<<<NTOK / 8, 256>>>(tmp, l1g + (size_t)l * 256,
                                         l1b + (size_t)l * 256);
        // FFN1: (65536 x 1024), K=256, ReLU + hi/lo out
        mma_gemm3<3><<<dim3(8, 512), 128, GSMEM>>>(
            xh, xl, w1h + (size_t)l * 1024 * 256, w1l + (size_t)l * 1024 * 256,
            b1 + (size_t)l * 1024, nullptr, fh, fl, 256, 1024);
        // FFN2: (65536 x 256), K=1024, fp32 out
        mma_gemm3<0><<<dim3(2, 512), 128, GSMEM>>>(
            fh, fl, w2h + (size_t)l * 256 * 1024, w2l + (size_t)l * 256 * 1024,
            b2 + (size_t)l * 256, tmp, nullptr, nullptr, 1024, 256);
        add_ln_kernel<<<NTOK / 8, 256>>>(tmp, l2g + (size_t)l * 256,
                                         l2b + (size_t)l * 256);
    }

    head_kernel<<<NWIN / 8, 256>>>(hw, hb, out);
}

// round 8
// speedup vs baseline: 1.2648x; 1.2648x over previous
#include <cuda_runtime.h>
#include <cuda_fp16.h>
#include <cstdint>

// ---------------------------------------------------------------------------
// SlidingWindowTransformer: B=4,S=512,D=256,W=32,L=4,H=8,DH=32,DFF=1024,NOUT=32
// Round 8: GEMM v4 — fp16 2-pass split (A = hi+lo fp16, B = single fp16):
//   C ≈ Ah*Bh + Al*Bh.  Dropped A*Bl term scale 2^-11; predicted rel_err ~2e-4.
// 33% less tensor work + 25% less smem traffic than bf16 3-pass (the measured
// binder). 3-stage cp.async pipeline (30KB/stage), warp tile 64x64, 4 warps.
// ---------------------------------------------------------------------------

namespace {
constexpr int Dm   = 256;
constexpr int DFF  = 1024;
constexpr int NWIN = 2048;            // B*S
constexpr int NTOK = NWIN * 32;       // 65536
constexpr float EPS   = 1e-5f;
constexpr float SCALE = 0.17677669529663687f;  // 32^-0.5
constexpr int GSMEM = 3 * 30720;      // 3 stages x (Ah,Al,Bh tiles x 10240B)
}

// fp32 scratch
__device__ float g_x  [(size_t)NTOK * Dm];
__device__ float g_qkv[(size_t)NTOK * 768];
__device__ float g_tmp[(size_t)NTOK * Dm];
// fp16 hi/lo activation scratch
__device__ __half g_xh[(size_t)NTOK * Dm];
__device__ __half g_xl[(size_t)NTOK * Dm];
__device__ __half g_ah[(size_t)NTOK * Dm];
__device__ __half g_al[(size_t)NTOK * Dm];
__device__ __half g_fh[(size_t)NTOK * DFF];
__device__ __half g_fl[(size_t)NTOK * DFF];
// fp16 weights (single precision stream; hi only)
__device__ __half g_winh[4 * 768 * 256];
__device__ __half g_woh [4 * 256 * 256];
__device__ __half g_w1h [4 * 1024 * 256];
__device__ __half g_w2h [4 * 256 * 1024];

// ---------------------------------------------------------------------------
// helpers
// ---------------------------------------------------------------------------
__device__ __forceinline__ void ldsm4(uint32_t* r, uint32_t addr) {
    asm volatile("ldmatrix.sync.aligned.m8n8.x4.shared.b16 {%0,%1,%2,%3}, [%4];"
                 : "=r"(r[0]), "=r"(r[1]), "=r"(r[2]), "=r"(r[3]) : "r"(addr));
}
__device__ __forceinline__ void mma16816(float* c, const uint32_t* a,
                                         uint32_t b0, uint32_t b1) {
    asm volatile(
        "mma.sync.aligned.m16n8k16.row.col.f32.f16.f16.f32 "
        "{%0,%1,%2,%3}, {%4,%5,%6,%7}, {%8,%9}, {%0,%1,%2,%3};"
        : "+f"(c[0]), "+f"(c[1]), "+f"(c[2]), "+f"(c[3])
        : "r"(a[0]), "r"(a[1]), "r"(a[2]), "r"(a[3]), "r"(b0), "r"(b1));
}
__device__ __forceinline__ void cp_async16(uint32_t dst, const void* src) {
    asm volatile("cp.async.cg.shared.global [%0], [%1], 16;"
                 :: "r"(dst), "l"(src) : "memory");
}
__device__ __forceinline__ uint32_t pack2h(__half a, __half b) {
    __half2 t{a, b};
    return *reinterpret_cast<uint32_t*>(&t);
}
__device__ __forceinline__ void split2h(float x, float y,
                                        uint32_t& hi, uint32_t& lo) {
    __half hx = __float2half(x);
    __half hy = __float2half(y);
    __half lx = __float2half(x - __half2float(hx));
    __half ly = __float2half(y - __half2float(hy));
    hi = pack2h(hx, hy);
    lo = pack2h(lx, ly);
}

// ---------------------------------------------------------------------------
// Weight prep: fp32 -> fp16 (single stream)
// ---------------------------------------------------------------------------
__global__ void prep_w(const float* __restrict__ src,
                       __half* __restrict__ dh, int n) {
    int i = blockIdx.x * 256 + threadIdx.x;
    if (i >= n) return;
    dh[i] = __float2half(src[i]);
}

// ---------------------------------------------------------------------------
// GEMM v4 (NT): C[M,N] = (Ah+Al)[M,K] @ Bh[N,K]^T + bias[N]
// MODE 0: fp32 out.  MODE 3: ReLU then fp16 hi/lo out.
// CTA 128x128, BK=32, 4 warps (2Mx2N), warp tile 64x64, cp.async 3-stage.
// Stage layout: Ah@0, Al@10240, Bh@20480 (rows padded to 80B).
// ---------------------------------------------------------------------------
template <int MODE>
__global__ void __launch_bounds__(128, 2) mma_gemm4(
    const __half* __restrict__ Ah, const __half* __restrict__ Al,
    const __half* __restrict__ Bh,
    const float* __restrict__ bias,
    float* __restrict__ C,
    __half* __restrict__ Ch, __half* __restrict__ Cl,
    int K, int N)
{
    extern __shared__ char smem[];
    const uint32_t sb0 = (uint32_t)__cvta_generic_to_shared(smem);

    const int tid  = threadIdx.x;
    const int lane = tid & 31;
    const int wid  = tid >> 5;
    const int bm   = blockIdx.y * 128;
    const int bn   = blockIdx.x * 128;
    const int m0   = (wid >> 1) * 64;
    const int n0   = (wid & 1) * 64;

    const int lrow = lane & 15;
    const int lch  = lane >> 4;
    uint32_t aOff[4], bOff[4];
#pragma unroll
    for (int i = 0; i < 4; i++) {
        aOff[i] = (uint32_t)((m0 + i * 16 + lrow) * 80 + lch * 16);
        bOff[i] = (uint32_t)((n0 + i * 16 + lrow) * 80 + lch * 16);
    }

    float c[4][8][4];
#pragma unroll
    for (int i = 0; i < 4; i++)
#pragma unroll
        for (int j = 0; j < 8; j++)
#pragma unroll
            for (int k = 0; k < 4; k++) c[i][j][k] = 0.f;

    auto load_stage = [&](int s, int k0) {
        uint32_t base = sb0 + s * 30720;
#pragma unroll
        for (int i = 0; i < 4; i++) {
            int cc  = tid + i * 128;        // chunk id 0..511
            int row = cc >> 2;
            int kc  = cc & 3;
            uint32_t d = base + (uint32_t)(row * 80 + kc * 16);
            size_t ao = (size_t)(bm + row) * K + k0 + kc * 8;
            size_t bo = (size_t)(bn + row) * K + k0 + kc * 8;
            cp_async16(d,         Ah + ao);
            cp_async16(d + 10240, Al + ao);
            cp_async16(d + 20480, Bh + bo);
        }
        asm volatile("cp.async.commit_group;" ::: "memory");
    };

    const int ntile = K >> 5;
    load_stage(0, 0);
    if (ntile > 1) load_stage(1, 32);
    int s = 0;
    for (int it = 0; it < ntile; it++) {
        if (it + 2 < ntile) {
            int s2 = s + 2; if (s2 >= 3) s2 -= 3;
            load_stage(s2, (it + 2) * 32);
            asm volatile("cp.async.wait_group 2;" ::: "memory");
        } else if (it + 1 < ntile) {
            asm volatile("cp.async.wait_group 1;" ::: "memory");
        } else {
            asm volatile("cp.async.wait_group 0;" ::: "memory");
        }
        __syncthreads();

        uint32_t base = sb0 + s * 30720;
#pragma unroll
        for (int ks = 0; ks < 2; ks++) {
            const uint32_t ko = ks * 32;
            uint32_t a[16], bh[16];
            ldsm4(a + 0,  base + aOff[0] + ko);
            ldsm4(a + 4,  base + aOff[1] + ko);
            ldsm4(a + 8,  base + aOff[2] + ko);
            ldsm4(a + 12, base + aOff[3] + ko);
            ldsm4(bh + 0,  base + 20480 + bOff[0] + ko);
            ldsm4(bh + 4,  base + 20480 + bOff[1] + ko);
            ldsm4(bh + 8,  base + 20480 + bOff[2] + ko);
            ldsm4(bh + 12, base + 20480 + bOff[3] + ko);
            // A_hi * B_hi
#pragma unroll
            for (int mi = 0; mi < 4; mi++)
#pragma unroll
                for (int j = 0; j < 8; j++) {
                    int g4 = (j >> 1) * 4, jj = j & 1;
                    mma16816(c[mi][j], a + mi * 4, bh[g4 + jj], bh[g4 + 2 + jj]);
                }
            // A_lo * B_hi
            ldsm4(a + 0,  base + 10240 + aOff[0] + ko);
            ldsm4(a + 4,  base + 10240 + aOff[1] + ko);
            ldsm4(a + 8,  base + 10240 + aOff[2] + ko);
            ldsm4(a + 12, base + 10240 + aOff[3] + ko);
#pragma unroll
            for (int mi = 0; mi < 4; mi++)
#pragma unroll
                for (int j = 0; j < 8; j++) {
                    int g4 = (j >> 1) * 4, jj = j & 1;
                    mma16816(c[mi][j], a + mi * 4, bh[g4 + jj], bh[g4 + 2 + jj]);
                }
        }
        __syncthreads();
        s = (s == 2) ? 0 : s + 1;
    }

    // epilogue
    const int g  = lane >> 2;
    const int t2 = lane & 3;
#pragma unroll
    for (int mi = 0; mi < 4; mi++) {
        int r0 = bm + m0 + mi * 16 + g;
#pragma unroll
        for (int j = 0; j < 8; j++) {
            int col = bn + n0 + j * 8 + t2 * 2;
            float2 bv = *reinterpret_cast<const float2*>(&bias[col]);
            float v0x = c[mi][j][0] + bv.x, v0y = c[mi][j][1] + bv.y;
            float v1x = c[mi][j][2] + bv.x, v1y = c[mi][j][3] + bv.y;
            if (MODE == 0) {
                *reinterpret_cast<float2*>(&C[(size_t)r0 * N + col]) =
                    make_float2(v0x, v0y);
                *reinterpret_cast<float2*>(&C[(size_t)(r0 + 8) * N + col]) =
                    make_float2(v1x, v1y);
            } else {
                v0x = fmaxf(v0x, 0.f); v0y = fmaxf(v0y, 0.f);
                v1x = fmaxf(v1x, 0.f); v1y = fmaxf(v1y, 0.f);
                uint32_t h0, l0, h1, l1;
                split2h(v0x, v0y, h0, l0);
                split2h(v1x, v1y, h1, l1);
                *reinterpret_cast<uint32_t*>(&Ch[(size_t)r0 * N + col])       = h0;
                *reinterpret_cast<uint32_t*>(&Cl[(size_t)r0 * N + col])       = l0;
                *reinterpret_cast<uint32_t*>(&Ch[(size_t)(r0 + 8) * N + col]) = h1;
                *reinterpret_cast<uint32_t*>(&Cl[(size_t)(r0 + 8) * N + col]) = l1;
            }
        }
    }
}

// ---------------------------------------------------------------------------
// Gather: g_x fp32 + fp16 hi/lo copies
// ---------------------------------------------------------------------------
__global__ void gather_kernel(const float* __restrict__ X,
                              const float* __restrict__ pos) {
    int idx = blockIdx.x * 256 + threadIdx.x;  // float4 index over NTOK*64
    int d4 = idx & 63;
    int w  = (idx >> 6) & 31;
    int n  = idx >> 11;
    int s  = n & 511;
    int b  = n >> 9;
    int src = s - w; if (src < 0) src = 0;
    float4 xv = reinterpret_cast<const float4*>(X)[(size_t)(b * 512 + src) * 64 + d4];
    float4 pv = reinterpret_cast<const float4*>(pos)[(size_t)w * 64 + d4];
    float4 o  = make_float4(xv.x + pv.x, xv.y + pv.y, xv.z + pv.z, xv.w + pv.w);
    reinterpret_cast<float4*>(g_x)[idx] = o;
    uint32_t h0, l0, h1, l1;
    split2h(o.x, o.y, h0, l0);
    split2h(o.z, o.w, h1, l1);
    *reinterpret_cast<uint2*>(&g_xh[(size_t)idx * 4]) = make_uint2(h0, h1);
    *reinterpret_cast<uint2*>(&g_xl[(size_t)idx * 4]) = make_uint2(l0, l1);
}

// ---------------------------------------------------------------------------
// Attention v2: block = (window, head), 128 threads. fp16 hi/lo output.
// ---------------------------------------------------------------------------
__global__ void attn_kernel2(const float* __restrict__ qkv,
                             __half* __restrict__ oh,
                             __half* __restrict__ ol) {
    __shared__ float qs[32][36];
    __shared__ float kT[32][36];   // kT[d][token]
    __shared__ float vs[32][36];
    __shared__ float ps[32][36];

    const int n   = blockIdx.x >> 3;
    const int h   = blockIdx.x & 7;
    const int tid = threadIdx.x;
    const int bse = n * 32;
    const int hc  = h * 32;

    for (int idx = tid; idx < 768; idx += 128) {
        int r = idx >> 3, c4 = idx & 7;
        int sect = r >> 5, tok = r & 31;
        float4 v = *reinterpret_cast<const float4*>(
            qkv + (size_t)(bse + tok) * 768 + sect * 256 + hc + c4 * 4);
        if (sect == 0) {
            *reinterpret_cast<float4*>(&qs[tok][c4 * 4]) = v;
        } else if (sect == 1) {
            kT[c4 * 4 + 0][tok] = v.x; kT[c4 * 4 + 1][tok] = v.y;
            kT[c4 * 4 + 2][tok] = v.z; kT[c4 * 4 + 3][tok] = v.w;
        } else {
            *reinterpret_cast<float4*>(&vs[tok][c4 * 4]) = v;
        }
    }
    __syncthreads();

    const int i  = tid >> 2;
    const int jc = tid & 3;

    float q[32];
#pragma unroll
    for (int u = 0; u < 8; u++) {
        float4 t = *reinterpret_cast<const float4*>(&qs[i][u * 4]);
        q[u * 4 + 0] = t.x * SCALE; q[u * 4 + 1] = t.y * SCALE;
        q[u * 4 + 2] = t.z * SCALE; q[u * 4 + 3] = t.w * SCALE;
    }
    float acc[8];
#pragma unroll
    for (int u = 0; u < 8; u++) acc[u] = 0.f;
#pragma unroll
    for (int d = 0; d < 32; d++) {
        float4 k0 = *reinterpret_cast<const float4*>(&kT[d][jc * 8]);
        float4 k1 = *reinterpret_cast<const float4*>(&kT[d][jc * 8 + 4]);
        float qd = q[d];
        acc[0] = fmaf(qd, k0.x, acc[0]); acc[1] = fmaf(qd, k0.y, acc[1]);
        acc[2] = fmaf(qd, k0.z, acc[2]); acc[3] = fmaf(qd, k0.w, acc[3]);
        acc[4] = fmaf(qd, k1.x, acc[4]); acc[5] = fmaf(qd, k1.y, acc[5]);
        acc[6] = fmaf(qd, k1.z, acc[6]); acc[7] = fmaf(qd, k1.w, acc[7]);
    }
    float mx = acc[0];
#pragma unroll
    for (int u = 1; u < 8; u++) mx = fmaxf(mx, acc[u]);
    mx = fmaxf(mx, __shfl_xor_sync(0xffffffffu, mx, 1));
    mx = fmaxf(mx, __shfl_xor_sync(0xffffffffu, mx, 2));
    float sum = 0.f;
#pragma unroll
    for (int u = 0; u < 8; u++) { acc[u] = __expf(acc[u] - mx); sum += acc[u]; }
    sum += __shfl_xor_sync(0xffffffffu, sum, 1);
    sum += __shfl_xor_sync(0xffffffffu, sum, 2);
    float inv = 1.f / sum;
#pragma unroll
    for (int u = 0; u < 8; u++) acc[u] *= inv;
    *reinterpret_cast<float4*>(&ps[i][jc * 8]) =
        make_float4(acc[0], acc[1], acc[2], acc[3]);
    *reinterpret_cast<float4*>(&ps[i][jc * 8 + 4]) =
        make_float4(acc[4], acc[5], acc[6], acc[7]);
    __syncthreads();

    float o[8];
#pragma unroll
    for (int u = 0; u < 8; u++) o[u] = 0.f;
#pragma unroll
    for (int j = 0; j < 32; j++) {
        float pj = ps[i][j];
        float4 v0 = *reinterpret_cast<const float4*>(&vs[j][jc * 8]);
        float4 v1 = *reinterpret_cast<const float4*>(&vs[j][jc * 8 + 4]);
        o[0] = fmaf(pj, v0.x, o[0]); o[1] = fmaf(pj, v0.y, o[1]);
        o[2] = fmaf(pj, v0.z, o[2]); o[3] = fmaf(pj, v0.w, o[3]);
        o[4] = fmaf(pj, v1.x, o[4]); o[5] = fmaf(pj, v1.y, o[5]);
        o[6] = fmaf(pj, v1.z, o[6]); o[7] = fmaf(pj, v1.w, o[7]);
    }
    uint32_t hp[4], lp[4];
    split2h(o[0], o[1], hp[0], lp[0]);
    split2h(o[2], o[3], hp[1], lp[1]);
    split2h(o[4], o[5], hp[2], lp[2]);
    split2h(o[6], o[7], hp[3], lp[3]);
    size_t base = (size_t)(bse + i) * 256 + hc + jc * 8;
    *reinterpret_cast<uint4*>(&oh[base]) = make_uint4(hp[0], hp[1], hp[2], hp[3]);
    *reinterpret_cast<uint4*>(&ol[base]) = make_uint4(lp[0], lp[1], lp[2], lp[3]);
}

// ---------------------------------------------------------------------------
// Residual add + LayerNorm: updates g_x fp32 and writes fp16 hi/lo copies.
// ---------------------------------------------------------------------------
__global__ void add_ln_kernel(const float* __restrict__ y,
                              const float* __restrict__ gg,
                              const float* __restrict__ bb) {
    int warp  = threadIdx.x >> 5;
    int lane  = threadIdx.x & 31;
    int token = blockIdx.x * 8 + warp;
    int c0    = lane * 8;
    float* xr = g_x + (size_t)token * 256;
    const float* yr = y + (size_t)token * 256;

    float v[8];
    float4 x0 = *reinterpret_cast<const float4*>(xr + c0);
    float4 x1 = *reinterpret_cast<const float4*>(xr + c0 + 4);
    float4 y0 = *reinterpret_cast<const float4*>(yr + c0);
    float4 y1 = *reinterpret_cast<const float4*>(yr + c0 + 4);
    v[0] = x0.x + y0.x; v[1] = x0.y + y0.y; v[2] = x0.z + y0.z; v[3] = x0.w + y0.w;
    v[4] = x1.x + y1.x; v[5] = x1.y + y1.y; v[6] = x1.z + y1.z; v[7] = x1.w + y1.w;

    float s = 0.f;
#pragma unroll
    for (int j = 0; j < 8; j++) s += v[j];
#pragma unroll
    for (int o = 16; o > 0; o >>= 1) s += __shfl_xor_sync(0xffffffffu, s, o);
    float mu = s * (1.f / 256.f);
    float s2 = 0.f;
#pragma unroll
    for (int j = 0; j < 8; j++) { float d = v[j] - mu; s2 += d * d; }
#pragma unroll
    for (int o = 16; o > 0; o >>= 1) s2 += __shfl_xor_sync(0xffffffffu, s2, o);
    float rstd = rsqrtf(s2 * (1.f / 256.f) + EPS);

    float4 g0 = *reinterpret_cast<const float4*>(gg + c0);
    float4 g1 = *reinterpret_cast<const float4*>(gg + c0 + 4);
    float4 b0 = *reinterpret_cast<const float4*>(bb + c0);
    float4 b1 = *reinterpret_cast<const float4*>(bb + c0 + 4);
    float r[8];
    r[0] = (v[0] - mu) * rstd * g0.x + b0.x; r[1] = (v[1] - mu) * rstd * g0.y + b0.y;
    r[2] = (v[2] - mu) * rstd * g0.z + b0.z; r[3] = (v[3] - mu) * rstd * g0.w + b0.w;
    r[4] = (v[4] - mu) * rstd * g1.x + b1.x; r[5] = (v[5] - mu) * rstd * g1.y + b1.y;
    r[6] = (v[6] - mu) * rstd * g1.z + b1.z; r[7] = (v[7] - mu) * rstd * g1.w + b1.w;

    *reinterpret_cast<float4*>(xr + c0)     = make_float4(r[0], r[1], r[2], r[3]);
    *reinterpret_cast<float4*>(xr + c0 + 4) = make_float4(r[4], r[5], r[6], r[7]);
    uint32_t hp[4], lp[4];
    split2h(r[0], r[1], hp[0], lp[0]);
    split2h(r[2], r[3], hp[1], lp[1]);
    split2h(r[4], r[5], hp[2], lp[2]);
    split2h(r[6], r[7], hp[3], lp[3]);
    size_t base = (size_t)token * 256 + c0;
    *reinterpret_cast<uint4*>(&g_xh[base]) = make_uint4(hp[0], hp[1], hp[2], hp[3]);
    *reinterpret_cast<uint4*>(&g_xl[base]) = make_uint4(lp[0], lp[1], lp[2], lp[3]);
}

// ---------------------------------------------------------------------------
// Head
// ---------------------------------------------------------------------------
__global__ void head_kernel(const float* __restrict__ hw,
                            const float* __restrict__ hb,
                            float* __restrict__ out) {
    __shared__ float hws[32][257];
    __shared__ float xs[8][256];
    int tid = threadIdx.x;
    for (int idx = tid; idx < 32 * 256; idx += 256) {
        int c = idx >> 8, d = idx & 255;
        hws[c][d] = hw[idx];
    }
    int warp = tid >> 5, lane = tid & 31;
    int n = blockIdx.x * 8 + warp;
    const float* xr = g_x + (size_t)(n * 32 + 31) * 256;
#pragma unroll
    for (int j = 0; j < 8; j++) xs[warp][lane + j * 32] = xr[lane + j * 32];
    __syncthreads();

    float accum = hb[lane];
#pragma unroll 8
    for (int d = 0; d < 256; d++) accum = fmaf(xs[warp][d], hws[lane][d], accum);
    out[(size_t)n * 32 + lane] = accum;
}

// ---------------------------------------------------------------------------
// Launch
// ---------------------------------------------------------------------------
extern "C" void kernel_launch(void* const* d_in, const int* in_sizes, int n_in,
                              void* d_out, int out_size) {
    const float* X    = (const float*)d_in[0];
    const float* pos  = (const float*)d_in[3];
    const float* w_in = (const float*)d_in[4];
    const float* b_in = (const float*)d_in[5];
    const float* w_o  = (const float*)d_in[6];
    const float* b_o  = (const float*)d_in[7];
    const float* w1   = (const float*)d_in[8];
    const float* b1   = (const float*)d_in[9];
    const float* w2   = (const float*)d_in[10];
    const float* b2   = (const float*)d_in[11];
    const float* l1g  = (const float*)d_in[12];
    const float* l1b  = (const float*)d_in[13];
    const float* l2g  = (const float*)d_in[14];
    const float* l2b  = (const float*)d_in[15];
    const float* hw   = (const float*)d_in[16];
    const float* hb   = (const float*)d_in[17];
    float* out = (float*)d_out;

    void* p;
    cudaGetSymbolAddress(&p, g_qkv);  float* qkv = (float*)p;
    cudaGetSymbolAddress(&p, g_tmp);  float* tmp = (float*)p;
    cudaGetSymbolAddress(&p, g_xh);   __half* xh = (__half*)p;
    cudaGetSymbolAddress(&p, g_xl);   __half* xl = (__half*)p;
    cudaGetSymbolAddress(&p, g_ah);   __half* ah = (__half*)p;
    cudaGetSymbolAddress(&p, g_al);   __half* al = (__half*)p;
    cudaGetSymbolAddress(&p, g_fh);   __half* fh = (__half*)p;
    cudaGetSymbolAddress(&p, g_fl);   __half* fl = (__half*)p;
    cudaGetSymbolAddress(&p, g_winh); __half* winh = (__half*)p;
    cudaGetSymbolAddress(&p, g_woh);  __half* woh = (__half*)p;
    cudaGetSymbolAddress(&p, g_w1h);  __half* w1h = (__half*)p;
    cudaGetSymbolAddress(&p, g_w2h);  __half* w2h = (__half*)p;

    cudaFuncSetAttribute(mma_gemm4<0>,
        cudaFuncAttributeMaxDynamicSharedMemorySize, GSMEM);
    cudaFuncSetAttribute(mma_gemm4<3>,
        cudaFuncAttributeMaxDynamicSharedMemorySize, GSMEM);

    prep_w<<<(4 * 768 * 256 + 255) / 256, 256>>>(w_in, winh, 4 * 768 * 256);
    prep_w<<<(4 * 256 * 256 + 255) / 256, 256>>>(w_o, woh, 4 * 256 * 256);
    prep_w<<<(4 * 1024 * 256 + 255) / 256, 256>>>(w1, w1h, 4 * 1024 * 256);
    prep_w<<<(4 * 256 * 1024 + 255) / 256, 256>>>(w2, w2h, 4 * 256 * 1024);

    gather_kernel<<<NTOK * 64 / 256, 256>>>(X, pos);

    for (int l = 0; l < 4; l++) {
        // QKV: (65536 x 768), K=256, fp32 out for attn
        mma_gemm4<0><<<dim3(6, 512), 128, GSMEM>>>(
            xh, xl, winh + (size_t)l * 768 * 256,
            b_in + (size_t)l * 768, qkv, nullptr, nullptr, 256, 768);
        attn_kernel2<<<NWIN * 8, 128>>>(qkv, ah, al);
        // o-proj: (65536 x 256), K=256, fp32 out
        mma_gemm4<0><<<dim3(2, 512), 128, GSMEM>>>(
            ah, al, woh + (size_t)l * 256 * 256,
            b_o + (size_t)l * 256, tmp, nullptr, nullptr, 256, 256);
        add_ln_kernel<<<NTOK / 8, 256>>>(tmp, l1g + (size_t)l * 256,
                                         l1b + (size_t)l * 256);
        // FFN1: (65536 x 1024), K=256, ReLU + fp16 hi/lo out
        mma_gemm4<3><<<dim3(8, 512), 128, GSMEM>>>(
            xh, xl, w1h + (size_t)l * 1024 * 256,
            b1 + (size_t)l * 1024, nullptr, fh, fl, 256, 1024);
        // FFN2: (65536 x 256), K=1024, fp32 out
        mma_gemm4<0><<<dim3(2, 512), 128, GSMEM>>>(
            fh, fl, w2h + (size_t)l * 256 * 1024,
            b2 + (size_t)l * 256, tmp, nullptr, nullptr, 1024, 256);
        add_ln_kernel<<<NTOK / 8, 256>>>(tmp, l2g + (size_t)l * 256,
                                         l2b + (size_t)l * 256);
    }

    head_kernel<<<NWIN / 8, 256>>>(hw, hb, out);
}

// round 9
// speedup vs baseline: 1.9088x; 1.5092x over previous
#include <cuda_runtime.h>
#include <cuda_fp16.h>
#include <cstdint>

// ---------------------------------------------------------------------------
// SlidingWindowTransformer: B=4,S=512,D=256,W=32,L=4,H=8,DH=32,DFF=1024,NOUT=32
// Round 9: GEMM v5 — single-pass pure fp16 (C ≈ A_h * B_h, fp32 accum).
// Quadrature error model from measured R8 (8.4e-5 @ one dropped 2^-11 term)
// predicts ~1.2e-4 final. Halves MMA work, cuts smem traffic to 0.67x, and
// moves to a 4-stage cp.async pipeline (20.5KB/stage).
// ---------------------------------------------------------------------------

namespace {
constexpr int Dm   = 256;
constexpr int DFF  = 1024;
constexpr int NWIN = 2048;            // B*S
constexpr int NTOK = NWIN * 32;       // 65536
constexpr float EPS   = 1e-5f;
constexpr float SCALE = 0.17677669529663687f;  // 32^-0.5
constexpr int STAGE = 20480;          // A tile (10240) + B tile (10240)
constexpr int GSMEM = 4 * STAGE;      // 4-stage pipeline = 81920 B
}

// fp32 scratch
__device__ float g_x  [(size_t)NTOK * Dm];
__device__ float g_qkv[(size_t)NTOK * 768];
__device__ float g_tmp[(size_t)NTOK * Dm];
// fp16 activation scratch (single stream)
__device__ __half g_xh[(size_t)NTOK * Dm];
__device__ __half g_ah[(size_t)NTOK * Dm];
__device__ __half g_fh[(size_t)NTOK * DFF];
// fp16 weights
__device__ __half g_winh[4 * 768 * 256];
__device__ __half g_woh [4 * 256 * 256];
__device__ __half g_w1h [4 * 1024 * 256];
__device__ __half g_w2h [4 * 256 * 1024];

// ---------------------------------------------------------------------------
// helpers
// ---------------------------------------------------------------------------
__device__ __forceinline__ void ldsm4(uint32_t* r, uint32_t addr) {
    asm volatile("ldmatrix.sync.aligned.m8n8.x4.shared.b16 {%0,%1,%2,%3}, [%4];"
                 : "=r"(r[0]), "=r"(r[1]), "=r"(r[2]), "=r"(r[3]) : "r"(addr));
}
__device__ __forceinline__ void mma16816(float* c, const uint32_t* a,
                                         uint32_t b0, uint32_t b1) {
    asm volatile(
        "mma.sync.aligned.m16n8k16.row.col.f32.f16.f16.f32 "
        "{%0,%1,%2,%3}, {%4,%5,%6,%7}, {%8,%9}, {%0,%1,%2,%3};"
        : "+f"(c[0]), "+f"(c[1]), "+f"(c[2]), "+f"(c[3])
        : "r"(a[0]), "r"(a[1]), "r"(a[2]), "r"(a[3]), "r"(b0), "r"(b1));
}
__device__ __forceinline__ void cp_async16(uint32_t dst, const void* src) {
    asm volatile("cp.async.cg.shared.global [%0], [%1], 16;"
                 :: "r"(dst), "l"(src) : "memory");
}
__device__ __forceinline__ uint32_t pack2h(__half a, __half b) {
    __half2 t{a, b};
    return *reinterpret_cast<uint32_t*>(&t);
}
__device__ __forceinline__ uint32_t cvt2h(float x, float y) {
    return pack2h(__float2half(x), __float2half(y));
}

// ---------------------------------------------------------------------------
// Weight prep: fp32 -> fp16
// ---------------------------------------------------------------------------
__global__ void prep_w(const float* __restrict__ src,
                       __half* __restrict__ dh, int n) {
    int i = blockIdx.x * 256 + threadIdx.x;
    if (i >= n) return;
    dh[i] = __float2half(src[i]);
}

// ---------------------------------------------------------------------------
// GEMM v5 (NT): C[M,N] = Ah[M,K] @ Bh[N,K]^T + bias[N]
// MODE 0: fp32 out.  MODE 3: ReLU then fp16 out.
// CTA 128x128, BK=32, 4 warps (2Mx2N), warp tile 64x64, cp.async 4-stage.
// Stage layout: A@0, B@10240 (rows padded to 80B).
// ---------------------------------------------------------------------------
template <int MODE>
__global__ void __launch_bounds__(128, 2) mma_gemm5(
    const __half* __restrict__ Ah, const __half* __restrict__ Bh,
    const float* __restrict__ bias,
    float* __restrict__ C, __half* __restrict__ Ch,
    int K, int N)
{
    extern __shared__ char smem[];
    const uint32_t sb0 = (uint32_t)__cvta_generic_to_shared(smem);

    const int tid  = threadIdx.x;
    const int lane = tid & 31;
    const int wid  = tid >> 5;
    const int bm   = blockIdx.y * 128;
    const int bn   = blockIdx.x * 128;
    const int m0   = (wid >> 1) * 64;
    const int n0   = (wid & 1) * 64;

    const int lrow = lane & 15;
    const int lch  = lane >> 4;
    uint32_t aOff[4], bOff[4];
#pragma unroll
    for (int i = 0; i < 4; i++) {
        aOff[i] = (uint32_t)((m0 + i * 16 + lrow) * 80 + lch * 16);
        bOff[i] = (uint32_t)((n0 + i * 16 + lrow) * 80 + lch * 16) + 10240u;
    }

    float c[4][8][4];
#pragma unroll
    for (int i = 0; i < 4; i++)
#pragma unroll
        for (int j = 0; j < 8; j++)
#pragma unroll
            for (int k = 0; k < 4; k++) c[i][j][k] = 0.f;

    auto load_stage = [&](int s, int k0) {
        uint32_t base = sb0 + s * STAGE;
#pragma unroll
        for (int i = 0; i < 4; i++) {
            int cc  = tid + i * 128;        // chunk id 0..511
            int row = cc >> 2;
            int kc  = cc & 3;
            uint32_t d = base + (uint32_t)(row * 80 + kc * 16);
            size_t ao = (size_t)(bm + row) * K + k0 + kc * 8;
            size_t bo = (size_t)(bn + row) * K + k0 + kc * 8;
            cp_async16(d,         Ah + ao);
            cp_async16(d + 10240, Bh + bo);
        }
        asm volatile("cp.async.commit_group;" ::: "memory");
    };

    const int ntile = K >> 5;
    load_stage(0, 0);
    if (ntile > 1) load_stage(1, 32);
    if (ntile > 2) load_stage(2, 64);
    for (int it = 0; it < ntile; it++) {
        if (it + 3 < ntile) {
            load_stage((it + 3) & 3, (it + 3) * 32);
            asm volatile("cp.async.wait_group 3;" ::: "memory");
        } else if (it + 2 < ntile) {
            asm volatile("cp.async.wait_group 2;" ::: "memory");
        } else if (it + 1 < ntile) {
            asm volatile("cp.async.wait_group 1;" ::: "memory");
        } else {
            asm volatile("cp.async.wait_group 0;" ::: "memory");
        }
        __syncthreads();

        uint32_t base = sb0 + (it & 3) * STAGE;
#pragma unroll
        for (int ks = 0; ks < 2; ks++) {
            const uint32_t ko = ks * 32;
            uint32_t a[16], bh[16];
            ldsm4(a + 0,  base + aOff[0] + ko);
            ldsm4(a + 4,  base + aOff[1] + ko);
            ldsm4(a + 8,  base + aOff[2] + ko);
            ldsm4(a + 12, base + aOff[3] + ko);
            ldsm4(bh + 0,  base + bOff[0] + ko);
            ldsm4(bh + 4,  base + bOff[1] + ko);
            ldsm4(bh + 8,  base + bOff[2] + ko);
            ldsm4(bh + 12, base + bOff[3] + ko);
#pragma unroll
            for (int mi = 0; mi < 4; mi++)
#pragma unroll
                for (int j = 0; j < 8; j++) {
                    int g4 = (j >> 1) * 4, jj = j & 1;
                    mma16816(c[mi][j], a + mi * 4, bh[g4 + jj], bh[g4 + 2 + jj]);
                }
        }
        __syncthreads();
    }

    // epilogue
    const int g  = lane >> 2;
    const int t2 = lane & 3;
#pragma unroll
    for (int mi = 0; mi < 4; mi++) {
        int r0 = bm + m0 + mi * 16 + g;
#pragma unroll
        for (int j = 0; j < 8; j++) {
            int col = bn + n0 + j * 8 + t2 * 2;
            float2 bv = *reinterpret_cast<const float2*>(&bias[col]);
            float v0x = c[mi][j][0] + bv.x, v0y = c[mi][j][1] + bv.y;
            float v1x = c[mi][j][2] + bv.x, v1y = c[mi][j][3] + bv.y;
            if (MODE == 0) {
                *reinterpret_cast<float2*>(&C[(size_t)r0 * N + col]) =
                    make_float2(v0x, v0y);
                *reinterpret_cast<float2*>(&C[(size_t)(r0 + 8) * N + col]) =
                    make_float2(v1x, v1y);
            } else {
                v0x = fmaxf(v0x, 0.f); v0y = fmaxf(v0y, 0.f);
                v1x = fmaxf(v1x, 0.f); v1y = fmaxf(v1y, 0.f);
                *reinterpret_cast<uint32_t*>(&Ch[(size_t)r0 * N + col]) =
                    cvt2h(v0x, v0y);
                *reinterpret_cast<uint32_t*>(&Ch[(size_t)(r0 + 8) * N + col]) =
                    cvt2h(v1x, v1y);
            }
        }
    }
}

// ---------------------------------------------------------------------------
// Gather: g_x fp32 + fp16 copy
// ---------------------------------------------------------------------------
__global__ void gather_kernel(const float* __restrict__ X,
                              const float* __restrict__ pos) {
    int idx = blockIdx.x * 256 + threadIdx.x;  // float4 index over NTOK*64
    int d4 = idx & 63;
    int w  = (idx >> 6) & 31;
    int n  = idx >> 11;
    int s  = n & 511;
    int b  = n >> 9;
    int src = s - w; if (src < 0) src = 0;
    float4 xv = reinterpret_cast<const float4*>(X)[(size_t)(b * 512 + src) * 64 + d4];
    float4 pv = reinterpret_cast<const float4*>(pos)[(size_t)w * 64 + d4];
    float4 o  = make_float4(xv.x + pv.x, xv.y + pv.y, xv.z + pv.z, xv.w + pv.w);
    reinterpret_cast<float4*>(g_x)[idx] = o;
    *reinterpret_cast<uint2*>(&g_xh[(size_t)idx * 4]) =
        make_uint2(cvt2h(o.x, o.y), cvt2h(o.z, o.w));
}

// ---------------------------------------------------------------------------
// Attention v2: block = (window, head), 128 threads. fp16 output.
// ---------------------------------------------------------------------------
__global__ void attn_kernel2(const float* __restrict__ qkv,
                             __half* __restrict__ oh) {
    __shared__ float qs[32][36];
    __shared__ float kT[32][36];   // kT[d][token]
    __shared__ float vs[32][36];
    __shared__ float ps[32][36];

    const int n   = blockIdx.x >> 3;
    const int h   = blockIdx.x & 7;
    const int tid = threadIdx.x;
    const int bse = n * 32;
    const int hc  = h * 32;

    for (int idx = tid; idx < 768; idx += 128) {
        int r = idx >> 3, c4 = idx & 7;
        int sect = r >> 5, tok = r & 31;
        float4 v = *reinterpret_cast<const float4*>(
            qkv + (size_t)(bse + tok) * 768 + sect * 256 + hc + c4 * 4);
        if (sect == 0) {
            *reinterpret_cast<float4*>(&qs[tok][c4 * 4]) = v;
        } else if (sect == 1) {
            kT[c4 * 4 + 0][tok] = v.x; kT[c4 * 4 + 1][tok] = v.y;
            kT[c4 * 4 + 2][tok] = v.z; kT[c4 * 4 + 3][tok] = v.w;
        } else {
            *reinterpret_cast<float4*>(&vs[tok][c4 * 4]) = v;
        }
    }
    __syncthreads();

    const int i  = tid >> 2;
    const int jc = tid & 3;

    float q[32];
#pragma unroll
    for (int u = 0; u < 8; u++) {
        float4 t = *reinterpret_cast<const float4*>(&qs[i][u * 4]);
        q[u * 4 + 0] = t.x * SCALE; q[u * 4 + 1] = t.y * SCALE;
        q[u * 4 + 2] = t.z * SCALE; q[u * 4 + 3] = t.w * SCALE;
    }
    float acc[8];
#pragma unroll
    for (int u = 0; u < 8; u++) acc[u] = 0.f;
#pragma unroll
    for (int d = 0; d < 32; d++) {
        float4 k0 = *reinterpret_cast<const float4*>(&kT[d][jc * 8]);
        float4 k1 = *reinterpret_cast<const float4*>(&kT[d][jc * 8 + 4]);
        float qd = q[d];
        acc[0] = fmaf(qd, k0.x, acc[0]); acc[1] = fmaf(qd, k0.y, acc[1]);
        acc[2] = fmaf(qd, k0.z, acc[2]); acc[3] = fmaf(qd, k0.w, acc[3]);
        acc[4] = fmaf(qd, k1.x, acc[4]); acc[5] = fmaf(qd, k1.y, acc[5]);
        acc[6] = fmaf(qd, k1.z, acc[6]); acc[7] = fmaf(qd, k1.w, acc[7]);
    }
    float mx = acc[0];
#pragma unroll
    for (int u = 1; u < 8; u++) mx = fmaxf(mx, acc[u]);
    mx = fmaxf(mx, __shfl_xor_sync(0xffffffffu, mx, 1));
    mx = fmaxf(mx, __shfl_xor_sync(0xffffffffu, mx, 2));
    float sum = 0.f;
#pragma unroll
    for (int u = 0; u < 8; u++) { acc[u] = __expf(acc[u] - mx); sum += acc[u]; }
    sum += __shfl_xor_sync(0xffffffffu, sum, 1);
    sum += __shfl_xor_sync(0xffffffffu, sum, 2);
    float inv = 1.f / sum;
#pragma unroll
    for (int u = 0; u < 8; u++) acc[u] *= inv;
    *reinterpret_cast<float4*>(&ps[i][jc * 8]) =
        make_float4(acc[0], acc[1], acc[2], acc[3]);
    *reinterpret_cast<float4*>(&ps[i][jc * 8 + 4]) =
        make_float4(acc[4], acc[5], acc[6], acc[7]);
    __syncthreads();

    float o[8];
#pragma unroll
    for (int u = 0; u < 8; u++) o[u] = 0.f;
#pragma unroll
    for (int j = 0; j < 32; j++) {
        float pj = ps[i][j];
        float4 v0 = *reinterpret_cast<const float4*>(&vs[j][jc * 8]);
        float4 v1 = *reinterpret_cast<const float4*>(&vs[j][jc * 8 + 4]);
        o[0] = fmaf(pj, v0.x, o[0]); o[1] = fmaf(pj, v0.y, o[1]);
        o[2] = fmaf(pj, v0.z, o[2]); o[3] = fmaf(pj, v0.w, o[3]);
        o[4] = fmaf(pj, v1.x, o[4]); o[5] = fmaf(pj, v1.y, o[5]);
        o[6] = fmaf(pj, v1.z, o[6]); o[7] = fmaf(pj, v1.w, o[7]);
    }
    size_t base = (size_t)(bse + i) * 256 + hc + jc * 8;
    *reinterpret_cast<uint4*>(&oh[base]) =
        make_uint4(cvt2h(o[0], o[1]), cvt2h(o[2], o[3]),
                   cvt2h(o[4], o[5]), cvt2h(o[6], o[7]));
}

// ---------------------------------------------------------------------------
// Residual add + LayerNorm: updates g_x fp32 and writes fp16 copy.
// ---------------------------------------------------------------------------
__global__ void add_ln_kernel(const float* __restrict__ y,
                              const float* __restrict__ gg,
                              const float* __restrict__ bb) {
    int warp  = threadIdx.x >> 5;
    int lane  = threadIdx.x & 31;
    int token = blockIdx.x * 8 + warp;
    int c0    = lane * 8;
    float* xr = g_x + (size_t)token * 256;
    const float* yr = y + (size_t)token * 256;

    float v[8];
    float4 x0 = *reinterpret_cast<const float4*>(xr + c0);
    float4 x1 = *reinterpret_cast<const float4*>(xr + c0 + 4);
    float4 y0 = *reinterpret_cast<const float4*>(yr + c0);
    float4 y1 = *reinterpret_cast<const float4*>(yr + c0 + 4);
    v[0] = x0.x + y0.x; v[1] = x0.y + y0.y; v[2] = x0.z + y0.z; v[3] = x0.w + y0.w;
    v[4] = x1.x + y1.x; v[5] = x1.y + y1.y; v[6] = x1.z + y1.z; v[7] = x1.w + y1.w;

    float s = 0.f;
#pragma unroll
    for (int j = 0; j < 8; j++) s += v[j];
#pragma unroll
    for (int o = 16; o > 0; o >>= 1) s += __shfl_xor_sync(0xffffffffu, s, o);
    float mu = s * (1.f / 256.f);
    float s2 = 0.f;
#pragma unroll
    for (int j = 0; j < 8; j++) { float d = v[j] - mu; s2 += d * d; }
#pragma unroll
    for (int o = 16; o > 0; o >>= 1) s2 += __shfl_xor_sync(0xffffffffu, s2, o);
    float rstd = rsqrtf(s2 * (1.f / 256.f) + EPS);

    float4 g0 = *reinterpret_cast<const float4*>(gg + c0);
    float4 g1 = *reinterpret_cast<const float4*>(gg + c0 + 4);
    float4 b0 = *reinterpret_cast<const float4*>(bb + c0);
    float4 b1 = *reinterpret_cast<const float4*>(bb + c0 + 4);
    float r[8];
    r[0] = (v[0] - mu) * rstd * g0.x + b0.x; r[1] = (v[1] - mu) * rstd * g0.y + b0.y;
    r[2] = (v[2] - mu) * rstd * g0.z + b0.z; r[3] = (v[3] - mu) * rstd * g0.w + b0.w;
    r[4] = (v[4] - mu) * rstd * g1.x + b1.x; r[5] = (v[5] - mu) * rstd * g1.y + b1.y;
    r[6] = (v[6] - mu) * rstd * g1.z + b1.z; r[7] = (v[7] - mu) * rstd * g1.w + b1.w;

    *reinterpret_cast<float4*>(xr + c0)     = make_float4(r[0], r[1], r[2], r[3]);
    *reinterpret_cast<float4*>(xr + c0 + 4) = make_float4(r[4], r[5], r[6], r[7]);
    size_t base = (size_t)token * 256 + c0;
    *reinterpret_cast<uint4*>(&g_xh[base]) =
        make_uint4(cvt2h(r[0], r[1]), cvt2h(r[2], r[3]),
                   cvt2h(r[4], r[5]), cvt2h(r[6], r[7]));
}

// ---------------------------------------------------------------------------
// Head
// ---------------------------------------------------------------------------
__global__ void head_kernel(const float* __restrict__ hw,
                            const float* __restrict__ hb,
                            float* __restrict__ out) {
    __shared__ float hws[32][257];
    __shared__ float xs[8][256];
    int tid = threadIdx.x;
    for (int idx = tid; idx < 32 * 256; idx += 256) {
        int c = idx >> 8, d = idx & 255;
        hws[c][d] = hw[idx];
    }
    int warp = tid >> 5, lane = tid & 31;
    int n = blockIdx.x * 8 + warp;
    const float* xr = g_x + (size_t)(n * 32 + 31) * 256;
#pragma unroll
    for (int j = 0; j < 8; j++) xs[warp][lane + j * 32] = xr[lane + j * 32];
    __syncthreads();

    float accum = hb[lane];
#pragma unroll 8
    for (int d = 0; d < 256; d++) accum = fmaf(xs[warp][d], hws[lane][d], accum);
    out[(size_t)n * 32 + lane] = accum;
}

// ---------------------------------------------------------------------------
// Launch
// ---------------------------------------------------------------------------
extern "C" void kernel_launch(void* const* d_in, const int* in_sizes, int n_in,
                              void* d_out, int out_size) {
    const float* X    = (const float*)d_in[0];
    const float* pos  = (const float*)d_in[3];
    const float* w_in = (const float*)d_in[4];
    const float* b_in = (const float*)d_in[5];
    const float* w_o  = (const float*)d_in[6];
    const float* b_o  = (const float*)d_in[7];
    const float* w1   = (const float*)d_in[8];
    const float* b1   = (const float*)d_in[9];
    const float* w2   = (const float*)d_in[10];
    const float* b2   = (const float*)d_in[11];
    const float* l1g  = (const float*)d_in[12];
    const float* l1b  = (const float*)d_in[13];
    const float* l2g  = (const float*)d_in[14];
    const float* l2b  = (const float*)d_in[15];
    const float* hw   = (const float*)d_in[16];
    const float* hb   = (const float*)d_in[17];
    float* out = (float*)d_out;

    void* p;
    cudaGetSymbolAddress(&p, g_qkv);  float* qkv = (float*)p;
    cudaGetSymbolAddress(&p, g_tmp);  float* tmp = (float*)p;
    cudaGetSymbolAddress(&p, g_xh);   __half* xh = (__half*)p;
    cudaGetSymbolAddress(&p, g_ah);   __half* ah = (__half*)p;
    cudaGetSymbolAddress(&p, g_fh);   __half* fh = (__half*)p;
    cudaGetSymbolAddress(&p, g_winh); __half* winh = (__half*)p;
    cudaGetSymbolAddress(&p, g_woh);  __half* woh = (__half*)p;
    cudaGetSymbolAddress(&p, g_w1h);  __half* w1h = (__half*)p;
    cudaGetSymbolAddress(&p, g_w2h);  __half* w2h = (__half*)p;

    cudaFuncSetAttribute(mma_gemm5<0>,
        cudaFuncAttributeMaxDynamicSharedMemorySize, GSMEM);
    cudaFuncSetAttribute(mma_gemm5<3>,
        cudaFuncAttributeMaxDynamicSharedMemorySize, GSMEM);

    prep_w<<<(4 * 768 * 256 + 255) / 256, 256>>>(w_in, winh, 4 * 768 * 256);
    prep_w<<<(4 * 256 * 256 + 255) / 256, 256>>>(w_o, woh, 4 * 256 * 256);
    prep_w<<<(4 * 1024 * 256 + 255) / 256, 256>>>(w1, w1h, 4 * 1024 * 256);
    prep_w<<<(4 * 256 * 1024 + 255) / 256, 256>>>(w2, w2h, 4 * 256 * 1024);

    gather_kernel<<<NTOK * 64 / 256, 256>>>(X, pos);

    for (int l = 0; l < 4; l++) {
        // QKV: (65536 x 768), K=256, fp32 out for attn
        mma_gemm5<0><<<dim3(6, 512), 128, GSMEM>>>(
            xh, winh + (size_t)l * 768 * 256,
            b_in + (size_t)l * 768, qkv, nullptr, 256, 768);
        attn_kernel2<<<NWIN * 8, 128>>>(qkv, ah);
        // o-proj: (65536 x 256), K=256, fp32 out
        mma_gemm5<0><<<dim3(2, 512), 128, GSMEM>>>(
            ah, woh + (size_t)l * 256 * 256,
            b_o + (size_t)l * 256, tmp, nullptr, 256, 256);
        add_ln_kernel<<<NTOK / 8, 256>>>(tmp, l1g + (size_t)l * 256,
                                         l1b + (size_t)l * 256);
        // FFN1: (65536 x 1024), K=256, ReLU + fp16 out
        mma_gemm5<3><<<dim3(8, 512), 128, GSMEM>>>(
            xh, w1h + (size_t)l * 1024 * 256,
            b1 + (size_t)l * 1024, nullptr, fh, 256, 1024);
        // FFN2: (65536 x 256), K=1024, fp32 out
        mma_gemm5<0><<<dim3(2, 512), 128, GSMEM>>>(
            fh, w2h + (size_t)l * 256 * 1024,
            b2 + (size_t)l * 256, tmp, nullptr, 1024, 256);
        add_ln_kernel<<<NTOK / 8, 256>>>(tmp, l2g + (size_t)l * 256,
                                         l2b + (size_t)l * 256);
    }

    head_kernel<<<NWIN / 8, 256>>>(hw, hb, out);
}

// round 10
// speedup vs baseline: 2.0281x; 1.0625x over previous
#include <cuda_runtime.h>
#include <cuda_fp16.h>
#include <cstdint>

// ---------------------------------------------------------------------------
// SlidingWindowTransformer: B=4,S=512,D=256,W=32,L=4,H=8,DH=32,DFF=1024,NOUT=32
// Round 10:
//  - GEMM v6: occupancy 3 CTAs/SM (12 warps) — smem eff-BW scales with warps
//    (measured 29 B/cyc @8w vs 38 @16w). 3-stage pipeline, A-frag held 4 regs.
//  - All GEMM outputs fp16 (qkv + tmp buffers fp16): ~1.3 GB less DRAM.
// ---------------------------------------------------------------------------

namespace {
constexpr int Dm   = 256;
constexpr int DFF  = 1024;
constexpr int NWIN = 2048;            // B*S
constexpr int NTOK = NWIN * 32;       // 65536
constexpr float EPS   = 1e-5f;
constexpr float SCALE = 0.17677669529663687f;  // 32^-0.5
constexpr int STAGE = 20480;          // A tile (10240) + B tile (10240)
constexpr int GSMEM = 3 * STAGE;      // 61440 B; 3 CTAs/SM = 180 KB
}

// fp32 scratch
__device__ float g_x[(size_t)NTOK * Dm];       // residual base (fp32)
// fp16 scratch
__device__ __half g_qkv[(size_t)NTOK * 768];
__device__ __half g_tmp[(size_t)NTOK * Dm];
__device__ __half g_xh [(size_t)NTOK * Dm];
__device__ __half g_ah [(size_t)NTOK * Dm];
__device__ __half g_fh [(size_t)NTOK * DFF];
// fp16 weights
__device__ __half g_winh[4 * 768 * 256];
__device__ __half g_woh [4 * 256 * 256];
__device__ __half g_w1h [4 * 1024 * 256];
__device__ __half g_w2h [4 * 256 * 1024];

// ---------------------------------------------------------------------------
// helpers
// ---------------------------------------------------------------------------
__device__ __forceinline__ void ldsm4(uint32_t* r, uint32_t addr) {
    asm volatile("ldmatrix.sync.aligned.m8n8.x4.shared.b16 {%0,%1,%2,%3}, [%4];"
                 : "=r"(r[0]), "=r"(r[1]), "=r"(r[2]), "=r"(r[3]) : "r"(addr));
}
__device__ __forceinline__ void mma16816(float* c, const uint32_t* a,
                                         uint32_t b0, uint32_t b1) {
    asm volatile(
        "mma.sync.aligned.m16n8k16.row.col.f32.f16.f16.f32 "
        "{%0,%1,%2,%3}, {%4,%5,%6,%7}, {%8,%9}, {%0,%1,%2,%3};"
        : "+f"(c[0]), "+f"(c[1]), "+f"(c[2]), "+f"(c[3])
        : "r"(a[0]), "r"(a[1]), "r"(a[2]), "r"(a[3]), "r"(b0), "r"(b1));
}
__device__ __forceinline__ void cp_async16(uint32_t dst, const void* src) {
    asm volatile("cp.async.cg.shared.global [%0], [%1], 16;"
                 :: "r"(dst), "l"(src) : "memory");
}
__device__ __forceinline__ uint32_t cvt2h(float x, float y) {
    __half2 t{__float2half(x), __float2half(y)};
    return *reinterpret_cast<uint32_t*>(&t);
}

// ---------------------------------------------------------------------------
// Weight prep: fp32 -> fp16
// ---------------------------------------------------------------------------
__global__ void prep_w(const float* __restrict__ src,
                       __half* __restrict__ dh, int n) {
    int i = blockIdx.x * 256 + threadIdx.x;
    if (i >= n) return;
    dh[i] = __float2half(src[i]);
}

// ---------------------------------------------------------------------------
// GEMM v6 (NT): C[M,N] = Ah[M,K] @ Bh[N,K]^T + bias[N], fp16 out.
// RELU template flag. CTA 128x128, BK=32, 4 warps (2Mx2N), warp tile 64x64,
// cp.async 3-stage, 3 CTAs/SM. Stage: A@0, B@10240 (80B padded rows).
// ---------------------------------------------------------------------------
template <bool RELU>
__global__ void __launch_bounds__(128, 3) mma_gemm6(
    const __half* __restrict__ Ah, const __half* __restrict__ Bh,
    const float* __restrict__ bias, __half* __restrict__ Ch,
    int K, int N)
{
    extern __shared__ char smem[];
    const uint32_t sb0 = (uint32_t)__cvta_generic_to_shared(smem);

    const int tid  = threadIdx.x;
    const int lane = tid & 31;
    const int wid  = tid >> 5;
    const int bm   = blockIdx.y * 128;
    const int bn   = blockIdx.x * 128;
    const int m0   = (wid >> 1) * 64;
    const int n0   = (wid & 1) * 64;

    const int lrow = lane & 15;
    const int lch  = lane >> 4;
    uint32_t aOff[4], bOff[4];
#pragma unroll
    for (int i = 0; i < 4; i++) {
        aOff[i] = (uint32_t)((m0 + i * 16 + lrow) * 80 + lch * 16);
        bOff[i] = (uint32_t)((n0 + i * 16 + lrow) * 80 + lch * 16) + 10240u;
    }

    float c[4][8][4];
#pragma unroll
    for (int i = 0; i < 4; i++)
#pragma unroll
        for (int j = 0; j < 8; j++)
#pragma unroll
            for (int k = 0; k < 4; k++) c[i][j][k] = 0.f;

    auto load_stage = [&](int s, int k0) {
        uint32_t base = sb0 + s * STAGE;
#pragma unroll
        for (int i = 0; i < 4; i++) {
            int cc  = tid + i * 128;        // chunk id 0..511
            int row = cc >> 2;
            int kc  = cc & 3;
            uint32_t d = base + (uint32_t)(row * 80 + kc * 16);
            size_t ao = (size_t)(bm + row) * K + k0 + kc * 8;
            size_t bo = (size_t)(bn + row) * K + k0 + kc * 8;
            cp_async16(d,         Ah + ao);
            cp_async16(d + 10240, Bh + bo);
        }
        asm volatile("cp.async.commit_group;" ::: "memory");
    };

    const int ntile = K >> 5;
    load_stage(0, 0);
    if (ntile > 1) load_stage(1, 32);
    int s = 0;
    for (int it = 0; it < ntile; it++) {
        if (it + 2 < ntile) {
            int s2 = s + 2; if (s2 >= 3) s2 -= 3;
            load_stage(s2, (it + 2) * 32);
            asm volatile("cp.async.wait_group 2;" ::: "memory");
        } else if (it + 1 < ntile) {
            asm volatile("cp.async.wait_group 1;" ::: "memory");
        } else {
            asm volatile("cp.async.wait_group 0;" ::: "memory");
        }
        __syncthreads();

        uint32_t base = sb0 + s * STAGE;
#pragma unroll
        for (int ks = 0; ks < 2; ks++) {
            const uint32_t ko = ks * 32;
            uint32_t bh[16];
            ldsm4(bh + 0,  base + bOff[0] + ko);
            ldsm4(bh + 4,  base + bOff[1] + ko);
            ldsm4(bh + 8,  base + bOff[2] + ko);
            ldsm4(bh + 12, base + bOff[3] + ko);
            // A-fragment held as 4 regs per m-step (register pressure @occ3)
#pragma unroll
            for (int mi = 0; mi < 4; mi++) {
                uint32_t a[4];
                ldsm4(a, base + aOff[mi] + ko);
#pragma unroll
                for (int j = 0; j < 8; j++) {
                    int g4 = (j >> 1) * 4, jj = j & 1;
                    mma16816(c[mi][j], a, bh[g4 + jj], bh[g4 + 2 + jj]);
                }
            }
        }
        __syncthreads();
        s = (s == 2) ? 0 : s + 1;
    }

    // epilogue: bias (+ReLU), fp16 stores
    const int g  = lane >> 2;
    const int t2 = lane & 3;
#pragma unroll
    for (int mi = 0; mi < 4; mi++) {
        int r0 = bm + m0 + mi * 16 + g;
#pragma unroll
        for (int j = 0; j < 8; j++) {
            int col = bn + n0 + j * 8 + t2 * 2;
            float2 bv = *reinterpret_cast<const float2*>(&bias[col]);
            float v0x = c[mi][j][0] + bv.x, v0y = c[mi][j][1] + bv.y;
            float v1x = c[mi][j][2] + bv.x, v1y = c[mi][j][3] + bv.y;
            if (RELU) {
                v0x = fmaxf(v0x, 0.f); v0y = fmaxf(v0y, 0.f);
                v1x = fmaxf(v1x, 0.f); v1y = fmaxf(v1y, 0.f);
            }
            *reinterpret_cast<uint32_t*>(&Ch[(size_t)r0 * N + col]) =
                cvt2h(v0x, v0y);
            *reinterpret_cast<uint32_t*>(&Ch[(size_t)(r0 + 8) * N + col]) =
                cvt2h(v1x, v1y);
        }
    }
}

// ---------------------------------------------------------------------------
// Gather: g_x fp32 + fp16 copy
// ---------------------------------------------------------------------------
__global__ void gather_kernel(const float* __restrict__ X,
                              const float* __restrict__ pos) {
    int idx = blockIdx.x * 256 + threadIdx.x;  // float4 index over NTOK*64
    int d4 = idx & 63;
    int w  = (idx >> 6) & 31;
    int n  = idx >> 11;
    int s  = n & 511;
    int b  = n >> 9;
    int src = s - w; if (src < 0) src = 0;
    float4 xv = reinterpret_cast<const float4*>(X)[(size_t)(b * 512 + src) * 64 + d4];
    float4 pv = reinterpret_cast<const float4*>(pos)[(size_t)w * 64 + d4];
    float4 o  = make_float4(xv.x + pv.x, xv.y + pv.y, xv.z + pv.z, xv.w + pv.w);
    reinterpret_cast<float4*>(g_x)[idx] = o;
    *reinterpret_cast<uint2*>(&g_xh[(size_t)idx * 4]) =
        make_uint2(cvt2h(o.x, o.y), cvt2h(o.z, o.w));
}

// ---------------------------------------------------------------------------
// Attention v3: block = (window, head), 128 threads, fp16 qkv in, fp16 out.
// ---------------------------------------------------------------------------
__global__ void attn_kernel3(const __half* __restrict__ qkv,
                             __half* __restrict__ oh) {
    __shared__ float qs[32][36];
    __shared__ float kT[32][36];   // kT[d][token]
    __shared__ float vs[32][36];
    __shared__ float ps[32][36];

    const int n   = blockIdx.x >> 3;
    const int h   = blockIdx.x & 7;
    const int tid = threadIdx.x;
    const int bse = n * 32;
    const int hc  = h * 32;

    // staging: 3 sections x 32 tokens x 32 halves = 384 8-half chunks
    for (int idx = tid; idx < 384; idx += 128) {
        int c8 = idx & 3;              // 8-half chunk within 32
        int r  = idx >> 2;             // 0..95
        int sect = r >> 5, tok = r & 31;
        uint4 u = *reinterpret_cast<const uint4*>(
            qkv + (size_t)(bse + tok) * 768 + sect * 256 + hc + c8 * 8);
        const __half2* hp = reinterpret_cast<const __half2*>(&u);
        float f[8];
#pragma unroll
        for (int i = 0; i < 4; i++) {
            float2 t = __half22float2(hp[i]);
            f[i * 2] = t.x; f[i * 2 + 1] = t.y;
        }
        if (sect == 0) {
#pragma unroll
            for (int i = 0; i < 8; i++) qs[tok][c8 * 8 + i] = f[i];
        } else if (sect == 1) {
#pragma unroll
            for (int i = 0; i < 8; i++) kT[c8 * 8 + i][tok] = f[i];
        } else {
#pragma unroll
            for (int i = 0; i < 8; i++) vs[tok][c8 * 8 + i] = f[i];
        }
    }
    __syncthreads();

    const int i  = tid >> 2;
    const int jc = tid & 3;

    float q[32];
#pragma unroll
    for (int u = 0; u < 8; u++) {
        float4 t = *reinterpret_cast<const float4*>(&qs[i][u * 4]);
        q[u * 4 + 0] = t.x * SCALE; q[u * 4 + 1] = t.y * SCALE;
        q[u * 4 + 2] = t.z * SCALE; q[u * 4 + 3] = t.w * SCALE;
    }
    float acc[8];
#pragma unroll
    for (int u = 0; u < 8; u++) acc[u] = 0.f;
#pragma unroll
    for (int d = 0; d < 32; d++) {
        float4 k0 = *reinterpret_cast<const float4*>(&kT[d][jc * 8]);
        float4 k1 = *reinterpret_cast<const float4*>(&kT[d][jc * 8 + 4]);
        float qd = q[d];
        acc[0] = fmaf(qd, k0.x, acc[0]); acc[1] = fmaf(qd, k0.y, acc[1]);
        acc[2] = fmaf(qd, k0.z, acc[2]); acc[3] = fmaf(qd, k0.w, acc[3]);
        acc[4] = fmaf(qd, k1.x, acc[4]); acc[5] = fmaf(qd, k1.y, acc[5]);
        acc[6] = fmaf(qd, k1.z, acc[6]); acc[7] = fmaf(qd, k1.w, acc[7]);
    }
    float mx = acc[0];
#pragma unroll
    for (int u = 1; u < 8; u++) mx = fmaxf(mx, acc[u]);
    mx = fmaxf(mx, __shfl_xor_sync(0xffffffffu, mx, 1));
    mx = fmaxf(mx, __shfl_xor_sync(0xffffffffu, mx, 2));
    float sum = 0.f;
#pragma unroll
    for (int u = 0; u < 8; u++) { acc[u] = __expf(acc[u] - mx); sum += acc[u]; }
    sum += __shfl_xor_sync(0xffffffffu, sum, 1);
    sum += __shfl_xor_sync(0xffffffffu, sum, 2);
    float inv = 1.f / sum;
#pragma unroll
    for (int u = 0; u < 8; u++) acc[u] *= inv;
    *reinterpret_cast<float4*>(&ps[i][jc * 8]) =
        make_float4(acc[0], acc[1], acc[2], acc[3]);
    *reinterpret_cast<float4*>(&ps[i][jc * 8 + 4]) =
        make_float4(acc[4], acc[5], acc[6], acc[7]);
    __syncthreads();

    float o[8];
#pragma unroll
    for (int u = 0; u < 8; u++) o[u] = 0.f;
#pragma unroll
    for (int j = 0; j < 32; j++) {
        float pj = ps[i][j];
        float4 v0 = *reinterpret_cast<const float4*>(&vs[j][jc * 8]);
        float4 v1 = *reinterpret_cast<const float4*>(&vs[j][jc * 8 + 4]);
        o[0] = fmaf(pj, v0.x, o[0]); o[1] = fmaf(pj, v0.y, o[1]);
        o[2] = fmaf(pj, v0.z, o[2]); o[3] = fmaf(pj, v0.w, o[3]);
        o[4] = fmaf(pj, v1.x, o[4]); o[5] = fmaf(pj, v1.y, o[5]);
        o[6] = fmaf(pj, v1.z, o[6]); o[7] = fmaf(pj, v1.w, o[7]);
    }
    size_t base = (size_t)(bse + i) * 256 + hc + jc * 8;
    *reinterpret_cast<uint4*>(&oh[base]) =
        make_uint4(cvt2h(o[0], o[1]), cvt2h(o[2], o[3]),
                   cvt2h(o[4], o[5]), cvt2h(o[6], o[7]));
}

// ---------------------------------------------------------------------------
// Residual add + LayerNorm: y is fp16 now; updates g_x fp32 + fp16 copy.
// ---------------------------------------------------------------------------
__global__ void add_ln_kernel(const __half* __restrict__ y,
                              const float* __restrict__ gg,
                              const float* __restrict__ bb) {
    int warp  = threadIdx.x >> 5;
    int lane  = threadIdx.x & 31;
    int token = blockIdx.x * 8 + warp;
    int c0    = lane * 8;
    float* xr = g_x + (size_t)token * 256;

    uint4 yu = *reinterpret_cast<const uint4*>(y + (size_t)token * 256 + c0);
    const __half2* yp = reinterpret_cast<const __half2*>(&yu);
    float v[8];
    float4 x0 = *reinterpret_cast<const float4*>(xr + c0);
    float4 x1 = *reinterpret_cast<const float4*>(xr + c0 + 4);
    {
        float2 t0 = __half22float2(yp[0]);
        float2 t1 = __half22float2(yp[1]);
        float2 t2 = __half22float2(yp[2]);
        float2 t3 = __half22float2(yp[3]);
        v[0] = x0.x + t0.x; v[1] = x0.y + t0.y;
        v[2] = x0.z + t1.x; v[3] = x0.w + t1.y;
        v[4] = x1.x + t2.x; v[5] = x1.y + t2.y;
        v[6] = x1.z + t3.x; v[7] = x1.w + t3.y;
    }

    float s = 0.f;
#pragma unroll
    for (int j = 0; j < 8; j++) s += v[j];
#pragma unroll
    for (int o = 16; o > 0; o >>= 1) s += __shfl_xor_sync(0xffffffffu, s, o);
    float mu = s * (1.f / 256.f);
    float s2 = 0.f;
#pragma unroll
    for (int j = 0; j < 8; j++) { float d = v[j] - mu; s2 += d * d; }
#pragma unroll
    for (int o = 16; o > 0; o >>= 1) s2 += __shfl_xor_sync(0xffffffffu, s2, o);
    float rstd = rsqrtf(s2 * (1.f / 256.f) + EPS);

    float4 g0 = *reinterpret_cast<const float4*>(gg + c0);
    float4 g1 = *reinterpret_cast<const float4*>(gg + c0 + 4);
    float4 b0 = *reinterpret_cast<const float4*>(bb + c0);
    float4 b1 = *reinterpret_cast<const float4*>(bb + c0 + 4);
    float r[8];
    r[0] = (v[0] - mu) * rstd * g0.x + b0.x; r[1] = (v[1] - mu) * rstd * g0.y + b0.y;
    r[2] = (v[2] - mu) * rstd * g0.z + b0.z; r[3] = (v[3] - mu) * rstd * g0.w + b0.w;
    r[4] = (v[4] - mu) * rstd * g1.x + b1.x; r[5] = (v[5] - mu) * rstd * g1.y + b1.y;
    r[6] = (v[6] - mu) * rstd * g1.z + b1.z; r[7] = (v[7] - mu) * rstd * g1.w + b1.w;

    *reinterpret_cast<float4*>(xr + c0)     = make_float4(r[0], r[1], r[2], r[3]);
    *reinterpret_cast<float4*>(xr + c0 + 4) = make_float4(r[4], r[5], r[6], r[7]);
    size_t base = (size_t)token * 256 + c0;
    *reinterpret_cast<uint4*>(&g_xh[base]) =
        make_uint4(cvt2h(r[0], r[1]), cvt2h(r[2], r[3]),
                   cvt2h(r[4], r[5]), cvt2h(r[6], r[7]));
}

// ---------------------------------------------------------------------------
// Head
// ---------------------------------------------------------------------------
__global__ void head_kernel(const float* __restrict__ hw,
                            const float* __restrict__ hb,
                            float* __restrict__ out) {
    __shared__ float hws[32][257];
    __shared__ float xs[8][256];
    int tid = threadIdx.x;
    for (int idx = tid; idx < 32 * 256; idx += 256) {
        int c = idx >> 8, d = idx & 255;
        hws[c][d] = hw[idx];
    }
    int warp = tid >> 5, lane = tid & 31;
    int n = blockIdx.x * 8 + warp;
    const float* xr = g_x + (size_t)(n * 32 + 31) * 256;
#pragma unroll
    for (int j = 0; j < 8; j++) xs[warp][lane + j * 32] = xr[lane + j * 32];
    __syncthreads();

    float accum = hb[lane];
#pragma unroll 8
    for (int d = 0; d < 256; d++) accum = fmaf(xs[warp][d], hws[lane][d], accum);
    out[(size_t)n * 32 + lane] = accum;
}

// ---------------------------------------------------------------------------
// Launch
// ---------------------------------------------------------------------------
extern "C" void kernel_launch(void* const* d_in, const int* in_sizes, int n_in,
                              void* d_out, int out_size) {
    const float* X    = (const float*)d_in[0];
    const float* pos  = (const float*)d_in[3];
    const float* w_in = (const float*)d_in[4];
    const float* b_in = (const float*)d_in[5];
    const float* w_o  = (const float*)d_in[6];
    const float* b_o  = (const float*)d_in[7];
    const float* w1   = (const float*)d_in[8];
    const float* b1   = (const float*)d_in[9];
    const float* w2   = (const float*)d_in[10];
    const float* b2   = (const float*)d_in[11];
    const float* l1g  = (const float*)d_in[12];
    const float* l1b  = (const float*)d_in[13];
    const float* l2g  = (const float*)d_in[14];
    const float* l2b  = (const float*)d_in[15];
    const float* hw   = (const float*)d_in[16];
    const float* hb   = (const float*)d_in[17];
    float* out = (float*)d_out;

    void* p;
    cudaGetSymbolAddress(&p, g_qkv);  __half* qkv = (__half*)p;
    cudaGetSymbolAddress(&p, g_tmp);  __half* tmp = (__half*)p;
    cudaGetSymbolAddress(&p, g_xh);   __half* xh = (__half*)p;
    cudaGetSymbolAddress(&p, g_ah);   __half* ah = (__half*)p;
    cudaGetSymbolAddress(&p, g_fh);   __half* fh = (__half*)p;
    cudaGetSymbolAddress(&p, g_winh); __half* winh = (__half*)p;
    cudaGetSymbolAddress(&p, g_woh);  __half* woh = (__half*)p;
    cudaGetSymbolAddress(&p, g_w1h);  __half* w1h = (__half*)p;
    cudaGetSymbolAddress(&p, g_w2h);  __half* w2h = (__half*)p;

    cudaFuncSetAttribute(mma_gemm6<false>,
        cudaFuncAttributeMaxDynamicSharedMemorySize, GSMEM);
    cudaFuncSetAttribute(mma_gemm6<true>,
        cudaFuncAttributeMaxDynamicSharedMemorySize, GSMEM);

    prep_w<<<(4 * 768 * 256 + 255) / 256, 256>>>(w_in, winh, 4 * 768 * 256);
    prep_w<<<(4 * 256 * 256 + 255) / 256, 256>>>(w_o, woh, 4 * 256 * 256);
    prep_w<<<(4 * 1024 * 256 + 255) / 256, 256>>>(w1, w1h, 4 * 1024 * 256);
    prep_w<<<(4 * 256 * 1024 + 255) / 256, 256>>>(w2, w2h, 4 * 256 * 1024);

    gather_kernel<<<NTOK * 64 / 256, 256>>>(X, pos);

    for (int l = 0; l < 4; l++) {
        // QKV: (65536 x 768), K=256, fp16 out
        mma_gemm6<false><<<dim3(6, 512), 128, GSMEM>>>(
            xh, winh + (size_t)l * 768 * 256,
            b_in + (size_t)l * 768, qkv, 256, 768);
        attn_kernel3<<<NWIN * 8, 128>>>(qkv, ah);
        // o-proj: (65536 x 256), K=256, fp16 out
        mma_gemm6<false><<<dim3(2, 512), 128, GSMEM>>>(
            ah, woh + (size_t)l * 256 * 256,
            b_o + (size_t)l * 256, tmp, 256, 256);
        add_ln_kernel<<<NTOK / 8, 256>>>(tmp, l1g + (size_t)l * 256,
                                         l1b + (size_t)l * 256);
        // FFN1: (65536 x 1024), K=256, ReLU + fp16 out
        mma_gemm6<true><<<dim3(8, 512), 128, GSMEM>>>(
            xh, w1h + (size_t)l * 1024 * 256,
            b1 + (size_t)l * 1024, fh, 256, 1024);
        // FFN2: (65536 x 256), K=1024, fp16 out
        mma_gemm6<false><<<dim3(2, 512), 128, GSMEM>>>(
            fh, w2h + (size_t)l * 256 * 1024,
            b2 + (size_t)l * 256, tmp, 1024, 256);
        add_ln_kernel<<<NTOK / 8, 256>>>(tmp, l2g + (size_t)l * 256,
                                         l2b + (size_t)l * 256);
    }

    head_kernel<<<NWIN / 8, 256>>>(hw, hb, out);
}

// round 11
// speedup vs baseline: 2.0888x; 1.0299x over previous
#include <cuda_runtime.h>
#include <cuda_fp16.h>
#include <cstdint>

// ---------------------------------------------------------------------------
// SlidingWindowTransformer: B=4,S=512,D=256,W=32,L=4,H=8,DH=32,DFF=1024,NOUT=32
// Round 11: GEMM v7 — 16 warps/SM (8 warps x 64x32 tiles, 2 CTAs/SM; the only
// shape fitting the 128-reg cap) + BK=64 (halves barrier/fence count).
// The GEMM is latency/serialization bound: smem 31 B/cyc and 620 flop/cyc are
// both ~25% of peak; more warps + fewer syncs is the indicated fix.
// ---------------------------------------------------------------------------

namespace {
constexpr int Dm   = 256;
constexpr int DFF  = 1024;
constexpr int NWIN = 2048;            // B*S
constexpr int NTOK = NWIN * 32;       // 65536
constexpr float EPS   = 1e-5f;
constexpr float SCALE = 0.17677669529663687f;  // 32^-0.5
constexpr int TILEB = 18432;          // 128 rows x 144B (BK=64 fp16, padded)
constexpr int STAGE = 2 * TILEB;      // A + B = 36864
constexpr int GSMEM = 2 * STAGE;      // 2 stages = 73728; 2 CTAs/SM = 144KB
}

// fp32 scratch
__device__ float g_x[(size_t)NTOK * Dm];       // residual base (fp32)
// fp16 scratch
__device__ __half g_qkv[(size_t)NTOK * 768];
__device__ __half g_tmp[(size_t)NTOK * Dm];
__device__ __half g_xh [(size_t)NTOK * Dm];
__device__ __half g_ah [(size_t)NTOK * Dm];
__device__ __half g_fh [(size_t)NTOK * DFF];
// fp16 weights
__device__ __half g_winh[4 * 768 * 256];
__device__ __half g_woh [4 * 256 * 256];
__device__ __half g_w1h [4 * 1024 * 256];
__device__ __half g_w2h [4 * 256 * 1024];

// ---------------------------------------------------------------------------
// helpers
// ---------------------------------------------------------------------------
__device__ __forceinline__ void ldsm4(uint32_t* r, uint32_t addr) {
    asm volatile("ldmatrix.sync.aligned.m8n8.x4.shared.b16 {%0,%1,%2,%3}, [%4];"
                 : "=r"(r[0]), "=r"(r[1]), "=r"(r[2]), "=r"(r[3]) : "r"(addr));
}
__device__ __forceinline__ void mma16816(float* c, const uint32_t* a,
                                         uint32_t b0, uint32_t b1) {
    asm volatile(
        "mma.sync.aligned.m16n8k16.row.col.f32.f16.f16.f32 "
        "{%0,%1,%2,%3}, {%4,%5,%6,%7}, {%8,%9}, {%0,%1,%2,%3};"
        : "+f"(c[0]), "+f"(c[1]), "+f"(c[2]), "+f"(c[3])
        : "r"(a[0]), "r"(a[1]), "r"(a[2]), "r"(a[3]), "r"(b0), "r"(b1));
}
__device__ __forceinline__ void cp_async16(uint32_t dst, const void* src) {
    asm volatile("cp.async.cg.shared.global [%0], [%1], 16;"
                 :: "r"(dst), "l"(src) : "memory");
}
__device__ __forceinline__ uint32_t cvt2h(float x, float y) {
    __half2 t{__float2half(x), __float2half(y)};
    return *reinterpret_cast<uint32_t*>(&t);
}

// ---------------------------------------------------------------------------
// Weight prep: fp32 -> fp16
// ---------------------------------------------------------------------------
__global__ void prep_w(const float* __restrict__ src,
                       __half* __restrict__ dh, int n) {
    int i = blockIdx.x * 256 + threadIdx.x;
    if (i >= n) return;
    dh[i] = __float2half(src[i]);
}

// ---------------------------------------------------------------------------
// GEMM v7 (NT): C[M,N] = Ah[M,K] @ Bh[N,K]^T + bias[N], fp16 out, opt ReLU.
// CTA 128x128, BK=64, 256 threads, 8 warps (2Mx4N), warp tile 64x32,
// cp.async 2-stage, 2 CTAs/SM (16 warps). Stage: A@0, B@18432, 144B rows.
// ---------------------------------------------------------------------------
template <bool RELU>
__global__ void __launch_bounds__(256, 2) mma_gemm7(
    const __half* __restrict__ Ah, const __half* __restrict__ Bh,
    const float* __restrict__ bias, __half* __restrict__ Ch,
    int K, int N)
{
    extern __shared__ char smem[];
    const uint32_t sb0 = (uint32_t)__cvta_generic_to_shared(smem);

    const int tid  = threadIdx.x;
    const int lane = tid & 31;
    const int wid  = tid >> 5;
    const int bm   = blockIdx.y * 128;
    const int bn   = blockIdx.x * 128;
    const int m0   = (wid >> 2) * 64;
    const int n0   = (wid & 3) * 32;

    const int lrow = lane & 15;
    const int lch  = lane >> 4;
    uint32_t aOff[4], bOff[2];
#pragma unroll
    for (int i = 0; i < 4; i++)
        aOff[i] = (uint32_t)((m0 + i * 16 + lrow) * 144 + lch * 16);
#pragma unroll
    for (int i = 0; i < 2; i++)
        bOff[i] = (uint32_t)((n0 + i * 16 + lrow) * 144 + lch * 16) + (uint32_t)TILEB;

    float c[4][4][4];
#pragma unroll
    for (int i = 0; i < 4; i++)
#pragma unroll
        for (int j = 0; j < 4; j++)
#pragma unroll
            for (int k = 0; k < 4; k++) c[i][j][k] = 0.f;

    auto load_stage = [&](int s, int k0) {
        uint32_t base = sb0 + s * STAGE;
        // 2048 16B chunks: A = 128 rows x 8, B = same. 256 thr x 8 iters.
#pragma unroll
        for (int i = 0; i < 8; i++) {
            int cc   = tid + i * 256;
            int isB  = cc >> 10;           // 0 = A, 1 = B
            int wi   = cc & 1023;
            int row  = wi >> 3;
            int kc   = wi & 7;
            uint32_t d = base + (uint32_t)(isB * TILEB + row * 144 + kc * 16);
            const __half* src = isB
                ? (Bh + (size_t)(bn + row) * K + k0 + kc * 8)
                : (Ah + (size_t)(bm + row) * K + k0 + kc * 8);
            cp_async16(d, src);
        }
        asm volatile("cp.async.commit_group;" ::: "memory");
    };

    const int ntile = K >> 6;
    load_stage(0, 0);
    for (int it = 0; it < ntile; it++) {
        if (it + 1 < ntile) {
            load_stage((it + 1) & 1, (it + 1) * 64);
            asm volatile("cp.async.wait_group 1;" ::: "memory");
        } else {
            asm volatile("cp.async.wait_group 0;" ::: "memory");
        }
        __syncthreads();

        uint32_t base = sb0 + (it & 1) * STAGE;
#pragma unroll
        for (int ks = 0; ks < 4; ks++) {
            const uint32_t ko = ks * 32;
            uint32_t a[16], bh[8];
            ldsm4(a + 0,  base + aOff[0] + ko);
            ldsm4(a + 4,  base + aOff[1] + ko);
            ldsm4(a + 8,  base + aOff[2] + ko);
            ldsm4(a + 12, base + aOff[3] + ko);
            ldsm4(bh + 0, base + bOff[0] + ko);
            ldsm4(bh + 4, base + bOff[1] + ko);
#pragma unroll
            for (int mi = 0; mi < 4; mi++)
#pragma unroll
                for (int j = 0; j < 4; j++) {
                    int g4 = (j >> 1) * 4, jj = j & 1;
                    mma16816(c[mi][j], a + mi * 4, bh[g4 + jj], bh[g4 + 2 + jj]);
                }
        }
        __syncthreads();
    }

    // epilogue: bias (+ReLU), fp16 stores
    const int g  = lane >> 2;
    const int t2 = lane & 3;
#pragma unroll
    for (int mi = 0; mi < 4; mi++) {
        int r0 = bm + m0 + mi * 16 + g;
#pragma unroll
        for (int j = 0; j < 4; j++) {
            int col = bn + n0 + j * 8 + t2 * 2;
            float2 bv = *reinterpret_cast<const float2*>(&bias[col]);
            float v0x = c[mi][j][0] + bv.x, v0y = c[mi][j][1] + bv.y;
            float v1x = c[mi][j][2] + bv.x, v1y = c[mi][j][3] + bv.y;
            if (RELU) {
                v0x = fmaxf(v0x, 0.f); v0y = fmaxf(v0y, 0.f);
                v1x = fmaxf(v1x, 0.f); v1y = fmaxf(v1y, 0.f);
            }
            *reinterpret_cast<uint32_t*>(&Ch[(size_t)r0 * N + col]) =
                cvt2h(v0x, v0y);
            *reinterpret_cast<uint32_t*>(&Ch[(size_t)(r0 + 8) * N + col]) =
                cvt2h(v1x, v1y);
        }
    }
}

// ---------------------------------------------------------------------------
// Gather: g_x fp32 + fp16 copy
// ---------------------------------------------------------------------------
__global__ void gather_kernel(const float* __restrict__ X,
                              const float* __restrict__ pos) {
    int idx = blockIdx.x * 256 + threadIdx.x;  // float4 index over NTOK*64
    int d4 = idx & 63;
    int w  = (idx >> 6) & 31;
    int n  = idx >> 11;
    int s  = n & 511;
    int b  = n >> 9;
    int src = s - w; if (src < 0) src = 0;
    float4 xv = reinterpret_cast<const float4*>(X)[(size_t)(b * 512 + src) * 64 + d4];
    float4 pv = reinterpret_cast<const float4*>(pos)[(size_t)w * 64 + d4];
    float4 o  = make_float4(xv.x + pv.x, xv.y + pv.y, xv.z + pv.z, xv.w + pv.w);
    reinterpret_cast<float4*>(g_x)[idx] = o;
    *reinterpret_cast<uint2*>(&g_xh[(size_t)idx * 4]) =
        make_uint2(cvt2h(o.x, o.y), cvt2h(o.z, o.w));
}

// ---------------------------------------------------------------------------
// Attention v3: block = (window, head), 128 threads, fp16 qkv in, fp16 out.
// ---------------------------------------------------------------------------
__global__ void attn_kernel3(const __half* __restrict__ qkv,
                             __half* __restrict__ oh) {
    __shared__ float qs[32][36];
    __shared__ float kT[32][36];   // kT[d][token]
    __shared__ float vs[32][36];
    __shared__ float ps[32][36];

    const int n   = blockIdx.x >> 3;
    const int h   = blockIdx.x & 7;
    const int tid = threadIdx.x;
    const int bse = n * 32;
    const int hc  = h * 32;

    for (int idx = tid; idx < 384; idx += 128) {
        int c8 = idx & 3;
        int r  = idx >> 2;
        int sect = r >> 5, tok = r & 31;
        uint4 u = *reinterpret_cast<const uint4*>(
            qkv + (size_t)(bse + tok) * 768 + sect * 256 + hc + c8 * 8);
        const __half2* hp = reinterpret_cast<const __half2*>(&u);
        float f[8];
#pragma unroll
        for (int i = 0; i < 4; i++) {
            float2 t = __half22float2(hp[i]);
            f[i * 2] = t.x; f[i * 2 + 1] = t.y;
        }
        if (sect == 0) {
#pragma unroll
            for (int i = 0; i < 8; i++) qs[tok][c8 * 8 + i] = f[i];
        } else if (sect == 1) {
#pragma unroll
            for (int i = 0; i < 8; i++) kT[c8 * 8 + i][tok] = f[i];
        } else {
#pragma unroll
            for (int i = 0; i < 8; i++) vs[tok][c8 * 8 + i] = f[i];
        }
    }
    __syncthreads();

    const int i  = tid >> 2;
    const int jc = tid & 3;

    float q[32];
#pragma unroll
    for (int u = 0; u < 8; u++) {
        float4 t = *reinterpret_cast<const float4*>(&qs[i][u * 4]);
        q[u * 4 + 0] = t.x * SCALE; q[u * 4 + 1] = t.y * SCALE;
        q[u * 4 + 2] = t.z * SCALE; q[u * 4 + 3] = t.w * SCALE;
    }
    float acc[8];
#pragma unroll
    for (int u = 0; u < 8; u++) acc[u] = 0.f;
#pragma unroll
    for (int d = 0; d < 32; d++) {
        float4 k0 = *reinterpret_cast<const float4*>(&kT[d][jc * 8]);
        float4 k1 = *reinterpret_cast<const float4*>(&kT[d][jc * 8 + 4]);
        float qd = q[d];
        acc[0] = fmaf(qd, k0.x, acc[0]); acc[1] = fmaf(qd, k0.y, acc[1]);
        acc[2] = fmaf(qd, k0.z, acc[2]); acc[3] = fmaf(qd, k0.w, acc[3]);
        acc[4] = fmaf(qd, k1.x, acc[4]); acc[5] = fmaf(qd, k1.y, acc[5]);
        acc[6] = fmaf(qd, k1.z, acc[6]); acc[7] = fmaf(qd, k1.w, acc[7]);
    }
    float mx = acc[0];
#pragma unroll
    for (int u = 1; u < 8; u++) mx = fmaxf(mx, acc[u]);
    mx = fmaxf(mx, __shfl_xor_sync(0xffffffffu, mx, 1));
    mx = fmaxf(mx, __shfl_xor_sync(0xffffffffu, mx, 2));
    float sum = 0.f;
#pragma unroll
    for (int u = 0; u < 8; u++) { acc[u] = __expf(acc[u] - mx); sum += acc[u]; }
    sum += __shfl_xor_sync(0xffffffffu, sum, 1);
    sum += __shfl_xor_sync(0xffffffffu, sum, 2);
    float inv = 1.f / sum;
#pragma unroll
    for (int u = 0; u < 8; u++) acc[u] *= inv;
    *reinterpret_cast<float4*>(&ps[i][jc * 8]) =
        make_float4(acc[0], acc[1], acc[2], acc[3]);
    *reinterpret_cast<float4*>(&ps[i][jc * 8 + 4]) =
        make_float4(acc[4], acc[5], acc[6], acc[7]);
    __syncthreads();

    float o[8];
#pragma unroll
    for (int u = 0; u < 8; u++) o[u] = 0.f;
#pragma unroll
    for (int j = 0; j < 32; j++) {
        float pj = ps[i][j];
        float4 v0 = *reinterpret_cast<const float4*>(&vs[j][jc * 8]);
        float4 v1 = *reinterpret_cast<const float4*>(&vs[j][jc * 8 + 4]);
        o[0] = fmaf(pj, v0.x, o[0]); o[1] = fmaf(pj, v0.y, o[1]);
        o[2] = fmaf(pj, v0.z, o[2]); o[3] = fmaf(pj, v0.w, o[3]);
        o[4] = fmaf(pj, v1.x, o[4]); o[5] = fmaf(pj, v1.y, o[5]);
        o[6] = fmaf(pj, v1.z, o[6]); o[7] = fmaf(pj, v1.w, o[7]);
    }
    size_t base = (size_t)(bse + i) * 256 + hc + jc * 8;
    *reinterpret_cast<uint4*>(&oh[base]) =
        make_uint4(cvt2h(o[0], o[1]), cvt2h(o[2], o[3]),
                   cvt2h(o[4], o[5]), cvt2h(o[6], o[7]));
}

// ---------------------------------------------------------------------------
// Residual add + LayerNorm: fp16 y in; updates g_x fp32 + fp16 copy.
// ---------------------------------------------------------------------------
__global__ void add_ln_kernel(const __half* __restrict__ y,
                              const float* __restrict__ gg,
                              const float* __restrict__ bb) {
    int warp  = threadIdx.x >> 5;
    int lane  = threadIdx.x & 31;
    int token = blockIdx.x * 8 + warp;
    int c0    = lane * 8;
    float* xr = g_x + (size_t)token * 256;

    uint4 yu = *reinterpret_cast<const uint4*>(y + (size_t)token * 256 + c0);
    const __half2* yp = reinterpret_cast<const __half2*>(&yu);
    float v[8];
    float4 x0 = *reinterpret_cast<const float4*>(xr + c0);
    float4 x1 = *reinterpret_cast<const float4*>(xr + c0 + 4);
    {
        float2 t0 = __half22float2(yp[0]);
        float2 t1 = __half22float2(yp[1]);
        float2 t2 = __half22float2(yp[2]);
        float2 t3 = __half22float2(yp[3]);
        v[0] = x0.x + t0.x; v[1] = x0.y + t0.y;
        v[2] = x0.z + t1.x; v[3] = x0.w + t1.y;
        v[4] = x1.x + t2.x; v[5] = x1.y + t2.y;
        v[6] = x1.z + t3.x; v[7] = x1.w + t3.y;
    }

    float s = 0.f;
#pragma unroll
    for (int j = 0; j < 8; j++) s += v[j];
#pragma unroll
    for (int o = 16; o > 0; o >>= 1) s += __shfl_xor_sync(0xffffffffu, s, o);
    float mu = s * (1.f / 256.f);
    float s2 = 0.f;
#pragma unroll
    for (int j = 0; j < 8; j++) { float d = v[j] - mu; s2 += d * d; }
#pragma unroll
    for (int o = 16; o > 0; o >>= 1) s2 += __shfl_xor_sync(0xffffffffu, s2, o);
    float rstd = rsqrtf(s2 * (1.f / 256.f) + EPS);

    float4 g0 = *reinterpret_cast<const float4*>(gg + c0);
    float4 g1 = *reinterpret_cast<const float4*>(gg + c0 + 4);
    float4 b0 = *reinterpret_cast<const float4*>(bb + c0);
    float4 b1 = *reinterpret_cast<const float4*>(bb + c0 + 4);
    float r[8];
    r[0] = (v[0] - mu) * rstd * g0.x + b0.x; r[1] = (v[1] - mu) * rstd * g0.y + b0.y;
    r[2] = (v[2] - mu) * rstd * g0.z + b0.z; r[3] = (v[3] - mu) * rstd * g0.w + b0.w;
    r[4] = (v[4] - mu) * rstd * g1.x + b1.x; r[5] = (v[5] - mu) * rstd * g1.y + b1.y;
    r[6] = (v[6] - mu) * rstd * g1.z + b1.z; r[7] = (v[7] - mu) * rstd * g1.w + b1.w;

    *reinterpret_cast<float4*>(xr + c0)     = make_float4(r[0], r[1], r[2], r[3]);
    *reinterpret_cast<float4*>(xr + c0 + 4) = make_float4(r[4], r[5], r[6], r[7]);
    size_t base = (size_t)token * 256 + c0;
    *reinterpret_cast<uint4*>(&g_xh[base]) =
        make_uint4(cvt2h(r[0], r[1]), cvt2h(r[2], r[3]),
                   cvt2h(r[4], r[5]), cvt2h(r[6], r[7]));
}

// ---------------------------------------------------------------------------
// Head
// ---------------------------------------------------------------------------
__global__ void head_kernel(const float* __restrict__ hw,
                            const float* __restrict__ hb,
                            float* __restrict__ out) {
    __shared__ float hws[32][257];
    __shared__ float xs[8][256];
    int tid = threadIdx.x;
    for (int idx = tid; idx < 32 * 256; idx += 256) {
        int c = idx >> 8, d = idx & 255;
        hws[c][d] = hw[idx];
    }
    int warp = tid >> 5, lane = tid & 31;
    int n = blockIdx.x * 8 + warp;
    const float* xr = g_x + (size_t)(n * 32 + 31) * 256;
#pragma unroll
    for (int j = 0; j < 8; j++) xs[warp][lane + j * 32] = xr[lane + j * 32];
    __syncthreads();

    float accum = hb[lane];
#pragma unroll 8
    for (int d = 0; d < 256; d++) accum = fmaf(xs[warp][d], hws[lane][d], accum);
    out[(size_t)n * 32 + lane] = accum;
}

// ---------------------------------------------------------------------------
// Launch
// ---------------------------------------------------------------------------
extern "C" void kernel_launch(void* const* d_in, const int* in_sizes, int n_in,
                              void* d_out, int out_size) {
    const float* X    = (const float*)d_in[0];
    const float* pos  = (const float*)d_in[3];
    const float* w_in = (const float*)d_in[4];
    const float* b_in = (const float*)d_in[5];
    const float* w_o  = (const float*)d_in[6];
    const float* b_o  = (const float*)d_in[7];
    const float* w1   = (const float*)d_in[8];
    const float* b1   = (const float*)d_in[9];
    const float* w2   = (const float*)d_in[10];
    const float* b2   = (const float*)d_in[11];
    const float* l1g  = (const float*)d_in[12];
    const float* l1b  = (const float*)d_in[13];
    const float* l2g  = (const float*)d_in[14];
    const float* l2b  = (const float*)d_in[15];
    const float* hw   = (const float*)d_in[16];
    const float* hb   = (const float*)d_in[17];
    float* out = (float*)d_out;

    void* p;
    cudaGetSymbolAddress(&p, g_qkv);  __half* qkv = (__half*)p;
    cudaGetSymbolAddress(&p, g_tmp);  __half* tmp = (__half*)p;
    cudaGetSymbolAddress(&p, g_xh);   __half* xh = (__half*)p;
    cudaGetSymbolAddress(&p, g_ah);   __half* ah = (__half*)p;
    cudaGetSymbolAddress(&p, g_fh);   __half* fh = (__half*)p;
    cudaGetSymbolAddress(&p, g_winh); __half* winh = (__half*)p;
    cudaGetSymbolAddress(&p, g_woh);  __half* woh = (__half*)p;
    cudaGetSymbolAddress(&p, g_w1h);  __half* w1h = (__half*)p;
    cudaGetSymbolAddress(&p, g_w2h);  __half* w2h = (__half*)p;

    cudaFuncSetAttribute(mma_gemm7<false>,
        cudaFuncAttributeMaxDynamicSharedMemorySize, GSMEM);
    cudaFuncSetAttribute(mma_gemm7<true>,
        cudaFuncAttributeMaxDynamicSharedMemorySize, GSMEM);

    prep_w<<<(4 * 768 * 256 + 255) / 256, 256>>>(w_in, winh, 4 * 768 * 256);
    prep_w<<<(4 * 256 * 256 + 255) / 256, 256>>>(w_o, woh, 4 * 256 * 256);
    prep_w<<<(4 * 1024 * 256 + 255) / 256, 256>>>(w1, w1h, 4 * 1024 * 256);
    prep_w<<<(4 * 256 * 1024 + 255) / 256, 256>>>(w2, w2h, 4 * 256 * 1024);

    gather_kernel<<<NTOK * 64 / 256, 256>>>(X, pos);

    for (int l = 0; l < 4; l++) {
        // QKV: (65536 x 768), K=256, fp16 out
        mma_gemm7<false><<<dim3(6, 512), 256, GSMEM>>>(
            xh, winh + (size_t)l * 768 * 256,
            b_in + (size_t)l * 768, qkv, 256, 768);
        attn_kernel3<<<NWIN * 8, 128>>>(qkv, ah);
        // o-proj: (65536 x 256), K=256, fp16 out
        mma_gemm7<false><<<dim3(2, 512), 256, GSMEM>>>(
            ah, woh + (size_t)l * 256 * 256,
            b_o + (size_t)l * 256, tmp, 256, 256);
        add_ln_kernel<<<NTOK / 8, 256>>>(tmp, l1g + (size_t)l * 256,
                                         l1b + (size_t)l * 256);
        // FFN1: (65536 x 1024), K=256, ReLU + fp16 out
        mma_gemm7<true><<<dim3(8, 512), 256, GSMEM>>>(
            xh, w1h + (size_t)l * 1024 * 256,
            b1 + (size_t)l * 1024, fh, 256, 1024);
        // FFN2: (65536 x 256), K=1024, fp16 out
        mma_gemm7<false><<<dim3(2, 512), 256, GSMEM>>>(
            fh, w2h + (size_t)l * 256 * 1024,
            b2 + (size_t)l * 256, tmp, 1024, 256);
        add_ln_kernel<<<NTOK / 8, 256>>>(tmp, l2g + (size_t)l * 256,
                                         l2b + (size_t)l * 256);
    }

    head_kernel<<<NWIN / 8, 256>>>(hw, hb, out);
}

// round 12
// speedup vs baseline: 2.4916x; 1.1928x over previous
#include <cuda_runtime.h>
#include <cuda_fp16.h>
#include <cstdint>

// ---------------------------------------------------------------------------
// SlidingWindowTransformer: B=4,S=512,D=256,W=32,L=4,H=8,DH=32,DFF=1024,NOUT=32
// Round 12: structural work reduction (GEMM kernel itself = R11, unchanged):
//  - Layer-0 QKV factorized: (X[src]+pos)@W = (X@W)[src] + (pos@W)[w].
//    65536-row GEMM -> 2048-row GEMM + 32-row table; attn0 reads L2-resident T.
//  - Layer-3 output-sparse: only w=31 rows feed the head; o-proj/LN/FFN run
//    on M=2048 compacted rows (attention still sees all K/V).
// ---------------------------------------------------------------------------

namespace {
constexpr int Dm   = 256;
constexpr int DFF  = 1024;
constexpr int NWIN = 2048;            // B*S
constexpr int NTOK = NWIN * 32;       // 65536
constexpr float EPS   = 1e-5f;
constexpr float SCALE = 0.17677669529663687f;  // 32^-0.5
constexpr int TILEB = 18432;          // 128 rows x 144B (BK=64 fp16, padded)
constexpr int STAGE = 2 * TILEB;
constexpr int GSMEM = 2 * STAGE;      // 73728 B; 2 CTAs/SM
}

// fp32 scratch
__device__ float g_x [(size_t)NTOK * Dm];      // residual base (full rows)
__device__ float g_xc[(size_t)NWIN * Dm];      // layer-3 compact residual
__device__ float g_pq[32 * 768];               // pos @ Win^T (layer 0)
// fp16 scratch
__device__ __half g_qkv[(size_t)NTOK * 768];   // full qkv (l>=1) / T (l==0, 2048x768)
__device__ __half g_tmp[(size_t)NTOK * Dm];
__device__ __half g_xh [(size_t)NTOK * Dm];
__device__ __half g_xch[(size_t)NWIN * Dm];    // layer-3 compact fp16
__device__ __half g_ah [(size_t)NTOK * Dm];
__device__ __half g_fh [(size_t)NTOK * DFF];
__device__ __half g_xf [(size_t)NWIN * Dm];    // X flat fp16 (layer-0 T gemm)
// fp16 weights
__device__ __half g_winh[4 * 768 * 256];
__device__ __half g_woh [4 * 256 * 256];
__device__ __half g_w1h [4 * 1024 * 256];
__device__ __half g_w2h [4 * 256 * 1024];

// ---------------------------------------------------------------------------
// helpers
// ---------------------------------------------------------------------------
__device__ __forceinline__ void ldsm4(uint32_t* r, uint32_t addr) {
    asm volatile("ldmatrix.sync.aligned.m8n8.x4.shared.b16 {%0,%1,%2,%3}, [%4];"
                 : "=r"(r[0]), "=r"(r[1]), "=r"(r[2]), "=r"(r[3]) : "r"(addr));
}
__device__ __forceinline__ void mma16816(float* c, const uint32_t* a,
                                         uint32_t b0, uint32_t b1) {
    asm volatile(
        "mma.sync.aligned.m16n8k16.row.col.f32.f16.f16.f32 "
        "{%0,%1,%2,%3}, {%4,%5,%6,%7}, {%8,%9}, {%0,%1,%2,%3};"
        : "+f"(c[0]), "+f"(c[1]), "+f"(c[2]), "+f"(c[3])
        : "r"(a[0]), "r"(a[1]), "r"(a[2]), "r"(a[3]), "r"(b0), "r"(b1));
}
__device__ __forceinline__ void cp_async16(uint32_t dst, const void* src) {
    asm volatile("cp.async.cg.shared.global [%0], [%1], 16;"
                 :: "r"(dst), "l"(src) : "memory");
}
__device__ __forceinline__ uint32_t cvt2h(float x, float y) {
    __half2 t{__float2half(x), __float2half(y)};
    return *reinterpret_cast<uint32_t*>(&t);
}

// ---------------------------------------------------------------------------
// prep: fp32 -> fp16
// ---------------------------------------------------------------------------
__global__ void prep_w(const float* __restrict__ src,
                       __half* __restrict__ dh, int n) {
    int i = blockIdx.x * 256 + threadIdx.x;
    if (i >= n) return;
    dh[i] = __float2half(src[i]);
}

// pos @ Win^T (fp32, 32x768): thread = one (w,c) output.
__global__ void pq_kernel(const float* __restrict__ pos,
                          const float* __restrict__ w_in) {
    int idx = blockIdx.x * 256 + threadIdx.x;   // 0..24575
    if (idx >= 32 * 768) return;
    int w = idx / 768, c = idx % 768;
    const float* pr = pos + w * 256;
    const float* wr = w_in + (size_t)c * 256;
    float s = 0.f;
#pragma unroll 8
    for (int d = 0; d < 256; d++) s = fmaf(pr[d], wr[d], s);
    g_pq[idx] = s;
}

// ---------------------------------------------------------------------------
// GEMM (NT), R11-proven: C[M,N] = Ah[M,K] @ Bh[N,K]^T + bias[N], fp16 out.
// CTA 128x128, BK=64, 8 warps (2Mx4N, 64x32), 2-stage cp.async, 2 CTAs/SM.
// ---------------------------------------------------------------------------
template <bool RELU>
__global__ void __launch_bounds__(256, 2) mma_gemm7(
    const __half* __restrict__ Ah, const __half* __restrict__ Bh,
    const float* __restrict__ bias, __half* __restrict__ Ch,
    int K, int N)
{
    extern __shared__ char smem[];
    const uint32_t sb0 = (uint32_t)__cvta_generic_to_shared(smem);

    const int tid  = threadIdx.x;
    const int lane = tid & 31;
    const int wid  = tid >> 5;
    const int bm   = blockIdx.y * 128;
    const int bn   = blockIdx.x * 128;
    const int m0   = (wid >> 2) * 64;
    const int n0   = (wid & 3) * 32;

    const int lrow = lane & 15;
    const int lch  = lane >> 4;
    uint32_t aOff[4], bOff[2];
#pragma unroll
    for (int i = 0; i < 4; i++)
        aOff[i] = (uint32_t)((m0 + i * 16 + lrow) * 144 + lch * 16);
#pragma unroll
    for (int i = 0; i < 2; i++)
        bOff[i] = (uint32_t)((n0 + i * 16 + lrow) * 144 + lch * 16) + (uint32_t)TILEB;

    float c[4][4][4];
#pragma unroll
    for (int i = 0; i < 4; i++)
#pragma unroll
        for (int j = 0; j < 4; j++)
#pragma unroll
            for (int k = 0; k < 4; k++) c[i][j][k] = 0.f;

    auto load_stage = [&](int s, int k0) {
        uint32_t base = sb0 + s * STAGE;
#pragma unroll
        for (int i = 0; i < 8; i++) {
            int cc   = tid + i * 256;
            int isB  = cc >> 10;
            int wi   = cc & 1023;
            int row  = wi >> 3;
            int kc   = wi & 7;
            uint32_t d = base + (uint32_t)(isB * TILEB + row * 144 + kc * 16);
            const __half* src = isB
                ? (Bh + (size_t)(bn + row) * K + k0 + kc * 8)
                : (Ah + (size_t)(bm + row) * K + k0 + kc * 8);
            cp_async16(d, src);
        }
        asm volatile("cp.async.commit_group;" ::: "memory");
    };

    const int ntile = K >> 6;
    load_stage(0, 0);
    for (int it = 0; it < ntile; it++) {
        if (it + 1 < ntile) {
            load_stage((it + 1) & 1, (it + 1) * 64);
            asm volatile("cp.async.wait_group 1;" ::: "memory");
        } else {
            asm volatile("cp.async.wait_group 0;" ::: "memory");
        }
        __syncthreads();

        uint32_t base = sb0 + (it & 1) * STAGE;
#pragma unroll
        for (int ks = 0; ks < 4; ks++) {
            const uint32_t ko = ks * 32;
            uint32_t a[16], bh[8];
            ldsm4(a + 0,  base + aOff[0] + ko);
            ldsm4(a + 4,  base + aOff[1] + ko);
            ldsm4(a + 8,  base + aOff[2] + ko);
            ldsm4(a + 12, base + aOff[3] + ko);
            ldsm4(bh + 0, base + bOff[0] + ko);
            ldsm4(bh + 4, base + bOff[1] + ko);
#pragma unroll
            for (int mi = 0; mi < 4; mi++)
#pragma unroll
                for (int j = 0; j < 4; j++) {
                    int g4 = (j >> 1) * 4, jj = j & 1;
                    mma16816(c[mi][j], a + mi * 4, bh[g4 + jj], bh[g4 + 2 + jj]);
                }
        }
        __syncthreads();
    }

    const int g  = lane >> 2;
    const int t2 = lane & 3;
#pragma unroll
    for (int mi = 0; mi < 4; mi++) {
        int r0 = bm + m0 + mi * 16 + g;
#pragma unroll
        for (int j = 0; j < 4; j++) {
            int col = bn + n0 + j * 8 + t2 * 2;
            float2 bv = *reinterpret_cast<const float2*>(&bias[col]);
            float v0x = c[mi][j][0] + bv.x, v0y = c[mi][j][1] + bv.y;
            float v1x = c[mi][j][2] + bv.x, v1y = c[mi][j][3] + bv.y;
            if (RELU) {
                v0x = fmaxf(v0x, 0.f); v0y = fmaxf(v0y, 0.f);
                v1x = fmaxf(v1x, 0.f); v1y = fmaxf(v1y, 0.f);
            }
            *reinterpret_cast<uint32_t*>(&Ch[(size_t)r0 * N + col]) =
                cvt2h(v0x, v0y);
            *reinterpret_cast<uint32_t*>(&Ch[(size_t)(r0 + 8) * N + col]) =
                cvt2h(v1x, v1y);
        }
    }
}

// ---------------------------------------------------------------------------
// Gather: g_x fp32 (residual base). (fp16 copy no longer needed at layer 0.)
// ---------------------------------------------------------------------------
__global__ void gather_kernel(const float* __restrict__ X,
                              const float* __restrict__ pos) {
    int idx = blockIdx.x * 256 + threadIdx.x;
    int d4 = idx & 63;
    int w  = (idx >> 6) & 31;
    int n  = idx >> 11;
    int s  = n & 511;
    int b  = n >> 9;
    int src = s - w; if (src < 0) src = 0;
    float4 xv = reinterpret_cast<const float4*>(X)[(size_t)(b * 512 + src) * 64 + d4];
    float4 pv = reinterpret_cast<const float4*>(pos)[(size_t)w * 64 + d4];
    reinterpret_cast<float4*>(g_x)[idx] =
        make_float4(xv.x + pv.x, xv.y + pv.y, xv.z + pv.z, xv.w + pv.w);
}

// ---------------------------------------------------------------------------
// Attention core (shared by all variants): computes per-(window,head) softmax
// attention over smem-staged q/k/v and writes output.
// ---------------------------------------------------------------------------
__device__ __forceinline__ void attn_core(
    float (*qs)[36], float (*kT)[36], float (*vs)[36], float (*ps)[36],
    int tid, int bse, int hc, __half* oh, bool last)
{
    const int i  = tid >> 2;
    const int jc = tid & 3;

    float q[32];
#pragma unroll
    for (int u = 0; u < 8; u++) {
        float4 t = *reinterpret_cast<const float4*>(&qs[i][u * 4]);
        q[u * 4 + 0] = t.x * SCALE; q[u * 4 + 1] = t.y * SCALE;
        q[u * 4 + 2] = t.z * SCALE; q[u * 4 + 3] = t.w * SCALE;
    }
    float acc[8];
#pragma unroll
    for (int u = 0; u < 8; u++) acc[u] = 0.f;
#pragma unroll
    for (int d = 0; d < 32; d++) {
        float4 k0 = *reinterpret_cast<const float4*>(&kT[d][jc * 8]);
        float4 k1 = *reinterpret_cast<const float4*>(&kT[d][jc * 8 + 4]);
        float qd = q[d];
        acc[0] = fmaf(qd, k0.x, acc[0]); acc[1] = fmaf(qd, k0.y, acc[1]);
        acc[2] = fmaf(qd, k0.z, acc[2]); acc[3] = fmaf(qd, k0.w, acc[3]);
        acc[4] = fmaf(qd, k1.x, acc[4]); acc[5] = fmaf(qd, k1.y, acc[5]);
        acc[6] = fmaf(qd, k1.z, acc[6]); acc[7] = fmaf(qd, k1.w, acc[7]);
    }
    float mx = acc[0];
#pragma unroll
    for (int u = 1; u < 8; u++) mx = fmaxf(mx, acc[u]);
    mx = fmaxf(mx, __shfl_xor_sync(0xffffffffu, mx, 1));
    mx = fmaxf(mx, __shfl_xor_sync(0xffffffffu, mx, 2));
    float sum = 0.f;
#pragma unroll
    for (int u = 0; u < 8; u++) { acc[u] = __expf(acc[u] - mx); sum += acc[u]; }
    sum += __shfl_xor_sync(0xffffffffu, sum, 1);
    sum += __shfl_xor_sync(0xffffffffu, sum, 2);
    float inv = 1.f / sum;
#pragma unroll
    for (int u = 0; u < 8; u++) acc[u] *= inv;
    *reinterpret_cast<float4*>(&ps[i][jc * 8]) =
        make_float4(acc[0], acc[1], acc[2], acc[3]);
    *reinterpret_cast<float4*>(&ps[i][jc * 8 + 4]) =
        make_float4(acc[4], acc[5], acc[6], acc[7]);
    __syncthreads();

    if (last && i != 31) return;
    float o[8];
#pragma unroll
    for (int u = 0; u < 8; u++) o[u] = 0.f;
#pragma unroll
    for (int j = 0; j < 32; j++) {
        float pj = ps[i][j];
        float4 v0 = *reinterpret_cast<const float4*>(&vs[j][jc * 8]);
        float4 v1 = *reinterpret_cast<const float4*>(&vs[j][jc * 8 + 4]);
        o[0] = fmaf(pj, v0.x, o[0]); o[1] = fmaf(pj, v0.y, o[1]);
        o[2] = fmaf(pj, v0.z, o[2]); o[3] = fmaf(pj, v0.w, o[3]);
        o[4] = fmaf(pj, v1.x, o[4]); o[5] = fmaf(pj, v1.y, o[5]);
        o[6] = fmaf(pj, v1.z, o[6]); o[7] = fmaf(pj, v1.w, o[7]);
    }
    size_t base = last
        ? (size_t)(bse >> 5) * 256 + hc + jc * 8            // compact: row n
        : (size_t)(bse + i) * 256 + hc + jc * 8;            // full
    *reinterpret_cast<uint4*>(&oh[base]) =
        make_uint4(cvt2h(o[0], o[1]), cvt2h(o[2], o[3]),
                   cvt2h(o[4], o[5]), cvt2h(o[6], o[7]));
}

// Attention for layers 1..3 (full qkv input). LAST: only w=31 row, compact out.
template <bool LAST>
__global__ void attn_kernel3(const __half* __restrict__ qkv,
                             __half* __restrict__ oh) {
    __shared__ float qs[32][36];
    __shared__ float kT[32][36];
    __shared__ float vs[32][36];
    __shared__ float ps[32][36];

    const int n   = blockIdx.x >> 3;
    const int h   = blockIdx.x & 7;
    const int tid = threadIdx.x;
    const int bse = n * 32;
    const int hc  = h * 32;

    for (int idx = tid; idx < 384; idx += 128) {
        int c8 = idx & 3;
        int r  = idx >> 2;
        int sect = r >> 5, tok = r & 31;
        uint4 u = *reinterpret_cast<const uint4*>(
            qkv + (size_t)(bse + tok) * 768 + sect * 256 + hc + c8 * 8);
        const __half2* hp = reinterpret_cast<const __half2*>(&u);
        float f[8];
#pragma unroll
        for (int i = 0; i < 4; i++) {
            float2 t = __half22float2(hp[i]);
            f[i * 2] = t.x; f[i * 2 + 1] = t.y;
        }
        if (sect == 0) {
#pragma unroll
            for (int i = 0; i < 8; i++) qs[tok][c8 * 8 + i] = f[i];
        } else if (sect == 1) {
#pragma unroll
            for (int i = 0; i < 8; i++) kT[c8 * 8 + i][tok] = f[i];
        } else {
#pragma unroll
            for (int i = 0; i < 8; i++) vs[tok][c8 * 8 + i] = f[i];
        }
    }
    __syncthreads();
    attn_core(qs, kT, vs, ps, tid, bse, hc, oh, LAST);
}

// Attention for layer 0: qkv[n,w] = T[src(n,w)] + P[w], T = X@W (2048x768, L2).
__global__ void attn_kernel0(const __half* __restrict__ T,
                             __half* __restrict__ oh) {
    __shared__ float qs[32][36];
    __shared__ float kT[32][36];
    __shared__ float vs[32][36];
    __shared__ float ps[32][36];

    const int n   = blockIdx.x >> 3;
    const int h   = blockIdx.x & 7;
    const int tid = threadIdx.x;
    const int bse = n * 32;
    const int hc  = h * 32;
    const int s   = n & 511;
    const int b   = n >> 9;

    for (int idx = tid; idx < 384; idx += 128) {
        int c8 = idx & 3;
        int r  = idx >> 2;
        int sect = r >> 5, tok = r & 31;
        int src = s - tok; if (src < 0) src = 0;
        size_t off = (size_t)sect * 256 + hc + c8 * 8;
        uint4 u = *reinterpret_cast<const uint4*>(
            T + (size_t)(b * 512 + src) * 768 + off);
        const __half2* hp = reinterpret_cast<const __half2*>(&u);
        const float* pq = g_pq + (size_t)tok * 768 + off;
        float f[8];
#pragma unroll
        for (int i = 0; i < 4; i++) {
            float2 t = __half22float2(hp[i]);
            f[i * 2]     = t.x + pq[i * 2];
            f[i * 2 + 1] = t.y + pq[i * 2 + 1];
        }
        if (sect == 0) {
#pragma unroll
            for (int i = 0; i < 8; i++) qs[tok][c8 * 8 + i] = f[i];
        } else if (sect == 1) {
#pragma unroll
            for (int i = 0; i < 8; i++) kT[c8 * 8 + i][tok] = f[i];
        } else {
#pragma unroll
            for (int i = 0; i < 8; i++) vs[tok][c8 * 8 + i] = f[i];
        }
    }
    __syncthreads();
    attn_core(qs, kT, vs, ps, tid, bse, hc, oh, false);
}

// ---------------------------------------------------------------------------
// Residual add + LayerNorm (full rows): updates g_x fp32 + g_xh fp16.
// ---------------------------------------------------------------------------
__device__ __forceinline__ void ln_body(
    const float* vin, const float* gg, const float* bb, int c0, float* r)
{
    float s = 0.f;
#pragma unroll
    for (int j = 0; j < 8; j++) s += vin[j];
#pragma unroll
    for (int o = 16; o > 0; o >>= 1) s += __shfl_xor_sync(0xffffffffu, s, o);
    float mu = s * (1.f / 256.f);
    float s2 = 0.f;
#pragma unroll
    for (int j = 0; j < 8; j++) { float d = vin[j] - mu; s2 += d * d; }
#pragma unroll
    for (int o = 16; o > 0; o >>= 1) s2 += __shfl_xor_sync(0xffffffffu, s2, o);
    float rstd = rsqrtf(s2 * (1.f / 256.f) + EPS);
    float4 g0 = *reinterpret_cast<const float4*>(gg + c0);
    float4 g1 = *reinterpret_cast<const float4*>(gg + c0 + 4);
    float4 b0 = *reinterpret_cast<const float4*>(bb + c0);
    float4 b1 = *reinterpret_cast<const float4*>(bb + c0 + 4);
    r[0] = (vin[0] - mu) * rstd * g0.x + b0.x;
    r[1] = (vin[1] - mu) * rstd * g0.y + b0.y;
    r[2] = (vin[2] - mu) * rstd * g0.z + b0.z;
    r[3] = (vin[3] - mu) * rstd * g0.w + b0.w;
    r[4] = (vin[4] - mu) * rstd * g1.x + b1.x;
    r[5] = (vin[5] - mu) * rstd * g1.y + b1.y;
    r[6] = (vin[6] - mu) * rstd * g1.z + b1.z;
    r[7] = (vin[7] - mu) * rstd * g1.w + b1.w;
}

__global__ void add_ln_kernel(const __half* __restrict__ y,
                              const float* __restrict__ gg,
                              const float* __restrict__ bb) {
    int warp  = threadIdx.x >> 5;
    int lane  = threadIdx.x & 31;
    int token = blockIdx.x * 8 + warp;
    int c0    = lane * 8;
    float* xr = g_x + (size_t)token * 256;

    uint4 yu = *reinterpret_cast<const uint4*>(y + (size_t)token * 256 + c0);
    const __half2* yp = reinterpret_cast<const __half2*>(&yu);
    float v[8];
    float4 x0 = *reinterpret_cast<const float4*>(xr + c0);
    float4 x1 = *reinterpret_cast<const float4*>(xr + c0 + 4);
    {
        float2 t0 = __half22float2(yp[0]);
        float2 t1 = __half22float2(yp[1]);
        float2 t2 = __half22float2(yp[2]);
        float2 t3 = __half22float2(yp[3]);
        v[0] = x0.x + t0.x; v[1] = x0.y + t0.y;
        v[2] = x0.z + t1.x; v[3] = x0.w + t1.y;
        v[4] = x1.x + t2.x; v[5] = x1.y + t2.y;
        v[6] = x1.z + t3.x; v[7] = x1.w + t3.y;
    }
    float r[8];
    ln_body(v, gg, bb, c0, r);
    *reinterpret_cast<float4*>(xr + c0)     = make_float4(r[0], r[1], r[2], r[3]);
    *reinterpret_cast<float4*>(xr + c0 + 4) = make_float4(r[4], r[5], r[6], r[7]);
    size_t base = (size_t)token * 256 + c0;
    *reinterpret_cast<uint4*>(&g_xh[base]) =
        make_uint4(cvt2h(r[0], r[1]), cvt2h(r[2], r[3]),
                   cvt2h(r[4], r[5]), cvt2h(r[6], r[7]));
}

// Layer-3 compact LN: xin rows at arbitrary stride; writes g_xc + g_xch.
__global__ void add_ln_c(const __half* __restrict__ y,
                         const float* __restrict__ gg,
                         const float* __restrict__ bb,
                         const float* __restrict__ xin, int xstride) {
    int warp  = threadIdx.x >> 5;
    int lane  = threadIdx.x & 31;
    int token = blockIdx.x * 8 + warp;        // 0..2047
    int c0    = lane * 8;
    const float* xr = xin + (size_t)token * xstride;

    uint4 yu = *reinterpret_cast<const uint4*>(y + (size_t)token * 256 + c0);
    const __half2* yp = reinterpret_cast<const __half2*>(&yu);
    float v[8];
    float4 x0 = *reinterpret_cast<const float4*>(xr + c0);
    float4 x1 = *reinterpret_cast<const float4*>(xr + c0 + 4);
    {
        float2 t0 = __half22float2(yp[0]);
        float2 t1 = __half22float2(yp[1]);
        float2 t2 = __half22float2(yp[2]);
        float2 t3 = __half22float2(yp[3]);
        v[0] = x0.x + t0.x; v[1] = x0.y + t0.y;
        v[2] = x0.z + t1.x; v[3] = x0.w + t1.y;
        v[4] = x1.x + t2.x; v[5] = x1.y + t2.y;
        v[6] = x1.z + t3.x; v[7] = x1.w + t3.y;
    }
    float r[8];
    ln_body(v, gg, bb, c0, r);
    size_t base = (size_t)token * 256 + c0;
    *reinterpret_cast<float4*>(&g_xc[base])     = make_float4(r[0], r[1], r[2], r[3]);
    *reinterpret_cast<float4*>(&g_xc[base + 4]) = make_float4(r[4], r[5], r[6], r[7]);
    *reinterpret_cast<uint4*>(&g_xch[base]) =
        make_uint4(cvt2h(r[0], r[1]), cvt2h(r[2], r[3]),
                   cvt2h(r[4], r[5]), cvt2h(r[6], r[7]));
}

// ---------------------------------------------------------------------------
// Head: reads compact g_xc rows (one per window).
// ---------------------------------------------------------------------------
__global__ void head_kernel(const float* __restrict__ hw,
                            const float* __restrict__ hb,
                            float* __restrict__ out) {
    __shared__ float hws[32][257];
    __shared__ float xs[8][256];
    int tid = threadIdx.x;
    for (int idx = tid; idx < 32 * 256; idx += 256) {
        int c = idx >> 8, d = idx & 255;
        hws[c][d] = hw[idx];
    }
    int warp = tid >> 5, lane = tid & 31;
    int n = blockIdx.x * 8 + warp;
    const float* xr = g_xc + (size_t)n * 256;
#pragma unroll
    for (int j = 0; j < 8; j++) xs[warp][lane + j * 32] = xr[lane + j * 32];
    __syncthreads();

    float accum = hb[lane];
#pragma unroll 8
    for (int d = 0; d < 256; d++) accum = fmaf(xs[warp][d], hws[lane][d], accum);
    out[(size_t)n * 32 + lane] = accum;
}

// ---------------------------------------------------------------------------
// Launch
// ---------------------------------------------------------------------------
extern "C" void kernel_launch(void* const* d_in, const int* in_sizes, int n_in,
                              void* d_out, int out_size) {
    const float* X    = (const float*)d_in[0];
    const float* pos  = (const float*)d_in[3];
    const float* w_in = (const float*)d_in[4];
    const float* b_in = (const float*)d_in[5];
    const float* w_o  = (const float*)d_in[6];
    const float* b_o  = (const float*)d_in[7];
    const float* w1   = (const float*)d_in[8];
    const float* b1   = (const float*)d_in[9];
    const float* w2   = (const float*)d_in[10];
    const float* b2   = (const float*)d_in[11];
    const float* l1g  = (const float*)d_in[12];
    const float* l1b  = (const float*)d_in[13];
    const float* l2g  = (const float*)d_in[14];
    const float* l2b  = (const float*)d_in[15];
    const float* hw   = (const float*)d_in[16];
    const float* hb   = (const float*)d_in[17];
    float* out = (float*)d_out;

    void* p;
    cudaGetSymbolAddress(&p, g_qkv);  __half* qkv = (__half*)p;
    cudaGetSymbolAddress(&p, g_tmp);  __half* tmp = (__half*)p;
    cudaGetSymbolAddress(&p, g_xh);   __half* xh = (__half*)p;
    cudaGetSymbolAddress(&p, g_xch);  __half* xch = (__half*)p;
    cudaGetSymbolAddress(&p, g_ah);   __half* ah = (__half*)p;
    cudaGetSymbolAddress(&p, g_fh);   __half* fh = (__half*)p;
    cudaGetSymbolAddress(&p, g_xf);   __half* xf = (__half*)p;
    cudaGetSymbolAddress(&p, g_x);    float* gx = (float*)p;
    cudaGetSymbolAddress(&p, g_xc);   float* gxc = (float*)p;
    cudaGetSymbolAddress(&p, g_winh); __half* winh = (__half*)p;
    cudaGetSymbolAddress(&p, g_woh);  __half* woh = (__half*)p;
    cudaGetSymbolAddress(&p, g_w1h);  __half* w1h = (__half*)p;
    cudaGetSymbolAddress(&p, g_w2h);  __half* w2h = (__half*)p;

    cudaFuncSetAttribute(mma_gemm7<false>,
        cudaFuncAttributeMaxDynamicSharedMemorySize, GSMEM);
    cudaFuncSetAttribute(mma_gemm7<true>,
        cudaFuncAttributeMaxDynamicSharedMemorySize, GSMEM);

    prep_w<<<(4 * 768 * 256 + 255) / 256, 256>>>(w_in, winh, 4 * 768 * 256);
    prep_w<<<(4 * 256 * 256 + 255) / 256, 256>>>(w_o, woh, 4 * 256 * 256);
    prep_w<<<(4 * 1024 * 256 + 255) / 256, 256>>>(w1, w1h, 4 * 1024 * 256);
    prep_w<<<(4 * 256 * 1024 + 255) / 256, 256>>>(w2, w2h, 4 * 256 * 1024);
    prep_w<<<(NWIN * 256 + 255) / 256, 256>>>(X, xf, NWIN * 256);
    pq_kernel<<<(32 * 768 + 255) / 256, 256>>>(pos, w_in);

    gather_kernel<<<NTOK * 64 / 256, 256>>>(X, pos);

    for (int l = 0; l < 4; l++) {
        if (l == 0) {
            // T = Xflat @ Win^T (2048 x 768); attn0 expands T[src] + P[w]
            mma_gemm7<false><<<dim3(6, 16), 256, GSMEM>>>(
                xf, winh, b_in, qkv, 256, 768);
            attn_kernel0<<<NWIN * 8, 128>>>(qkv, ah);
        } else {
            mma_gemm7<false><<<dim3(6, 512), 256, GSMEM>>>(
                xh, winh + (size_t)l * 768 * 256,
                b_in + (size_t)l * 768, qkv, 256, 768);
            if (l < 3)
                attn_kernel3<false><<<NWIN * 8, 128>>>(qkv, ah);
            else
                attn_kernel3<true><<<NWIN * 8, 128>>>(qkv, ah);  // compact 2048 rows
        }
        if (l < 3) {
            mma_gemm7<false><<<dim3(2, 512), 256, GSMEM>>>(
                ah, woh + (size_t)l * 256 * 256,
                b_o + (size_t)l * 256, tmp, 256, 256);
            add_ln_kernel<<<NTOK / 8, 256>>>(tmp, l1g + (size_t)l * 256,
                                             l1b + (size_t)l * 256);
            mma_gemm7<true><<<dim3(8, 512), 256, GSMEM>>>(
                xh, w1h + (size_t)l * 1024 * 256,
                b1 + (size_t)l * 1024, fh, 256, 1024);
            mma_gemm7<false><<<dim3(2, 512), 256, GSMEM>>>(
                fh, w2h + (size_t)l * 256 * 1024,
                b2 + (size_t)l * 256, tmp, 1024, 256);
            add_ln_kernel<<<NTOK / 8, 256>>>(tmp, l2g + (size_t)l * 256,
                                             l2b + (size_t)l * 256);
        } else {
            // compact M = 2048 path (only w=31 rows feed the head)
            mma_gemm7<false><<<dim3(2, 16), 256, GSMEM>>>(
                ah, woh + (size_t)l * 256 * 256,
                b_o + (size_t)l * 256, tmp, 256, 256);
            add_ln_c<<<NWIN / 8, 256>>>(tmp, l1g + (size_t)l * 256,
                                        l1b + (size_t)l * 256,
                                        gx + 31 * 256, 32 * 256);
            mma_gemm7<true><<<dim3(8, 16), 256, GSMEM>>>(
                xch, w1h + (size_t)l * 1024 * 256,
                b1 + (size_t)l * 1024, fh, 256, 1024);
            mma_gemm7<false><<<dim3(2, 16), 256, GSMEM>>>(
                fh, w2h + (size_t)l * 256 * 1024,
                b2 + (size_t)l * 256, tmp, 1024, 256);
            add_ln_c<<<NWIN / 8, 256>>>(tmp, l2g + (size_t)l * 256,
                                        l2b + (size_t)l * 256,
                                        gxc, 256);
        }
    }

    head_kernel<<<NWIN / 8, 256>>>(hw, hb, out);
}

// round 13
// speedup vs baseline: 2.7461x; 1.1021x over previous
#include <cuda_runtime.h>
#include <cuda_fp16.h>
#include <cstdint>

// ---------------------------------------------------------------------------
// SlidingWindowTransformer: B=4,S=512,D=256,W=32,L=4,H=8,DH=32,DFF=1024,NOUT=32
// Round 13:
//  - fp16 residual unification: g_xh is both residual base and GEMM input
//    (fp32 g_x removed; add_ln traffic halved).
//  - Layer-3 QKV split: KV GEMM (N=512 full M) + compact Q GEMM (M=2048,
//    from w=31 rows copied inside layer-2 LN) + minimal attn_last kernel.
//  - Single prep launch so ncu -s 5 captures the o-proj GEMM.
// GEMM kernel = R11/R12 proven path, unchanged.
// ---------------------------------------------------------------------------

namespace {
constexpr int Dm   = 256;
constexpr int DFF  = 1024;
constexpr int NWIN = 2048;            // B*S
constexpr int NTOK = NWIN * 32;       // 65536
constexpr float EPS   = 1e-5f;
constexpr float SCALE = 0.17677669529663687f;  // 32^-0.5
constexpr int TILEB = 18432;          // 128 rows x 144B (BK=64 fp16, padded)
constexpr int STAGE = 2 * TILEB;
constexpr int GSMEM = 2 * STAGE;      // 73728 B; 2 CTAs/SM
}

// fp32 scratch
__device__ float g_pq[32 * 768];               // pos @ Win^T (layer 0)
// fp16 scratch
__device__ __half g_qkv[(size_t)NTOK * 768];   // qkv (l1,2) / kv N=512 (l3) / T (l0)
__device__ __half g_tmp[(size_t)NTOK * Dm];
__device__ __half g_xh [(size_t)NTOK * Dm];    // residual base + GEMM input
__device__ __half g_xq [(size_t)NWIN * Dm];    // compact w=31 copy of x2 (l3 Q in)
__device__ __half g_qc [(size_t)NWIN * Dm];    // l3 Q gemm out
__device__ __half g_xc [(size_t)NWIN * Dm];    // l3 compact activations
__device__ __half g_ah [(size_t)NTOK * Dm];
__device__ __half g_fh [(size_t)NTOK * DFF];
__device__ __half g_xf [(size_t)NWIN * Dm];    // X flat fp16 (layer-0 T gemm)
// fp16 weights
__device__ __half g_winh[4 * 768 * 256];
__device__ __half g_woh [4 * 256 * 256];
__device__ __half g_w1h [4 * 1024 * 256];
__device__ __half g_w2h [4 * 256 * 1024];

// ---------------------------------------------------------------------------
// helpers
// ---------------------------------------------------------------------------
__device__ __forceinline__ void ldsm4(uint32_t* r, uint32_t addr) {
    asm volatile("ldmatrix.sync.aligned.m8n8.x4.shared.b16 {%0,%1,%2,%3}, [%4];"
                 : "=r"(r[0]), "=r"(r[1]), "=r"(r[2]), "=r"(r[3]) : "r"(addr));
}
__device__ __forceinline__ void mma16816(float* c, const uint32_t* a,
                                         uint32_t b0, uint32_t b1) {
    asm volatile(
        "mma.sync.aligned.m16n8k16.row.col.f32.f16.f16.f32 "
        "{%0,%1,%2,%3}, {%4,%5,%6,%7}, {%8,%9}, {%0,%1,%2,%3};"
        : "+f"(c[0]), "+f"(c[1]), "+f"(c[2]), "+f"(c[3])
        : "r"(a[0]), "r"(a[1]), "r"(a[2]), "r"(a[3]), "r"(b0), "r"(b1));
}
__device__ __forceinline__ void cp_async16(uint32_t dst, const void* src) {
    asm volatile("cp.async.cg.shared.global [%0], [%1], 16;"
                 :: "r"(dst), "l"(src) : "memory");
}
__device__ __forceinline__ uint32_t cvt2h(float x, float y) {
    __half2 t{__float2half(x), __float2half(y)};
    return *reinterpret_cast<uint32_t*>(&t);
}
__device__ __forceinline__ void unpack8(uint4 u, float* f) {
    const __half2* hp = reinterpret_cast<const __half2*>(&u);
#pragma unroll
    for (int i = 0; i < 4; i++) {
        float2 t = __half22float2(hp[i]);
        f[i * 2] = t.x; f[i * 2 + 1] = t.y;
    }
}

// ---------------------------------------------------------------------------
// Single prep launch: all weights + X flat -> fp16
// ---------------------------------------------------------------------------
__global__ void prep_all(const float* __restrict__ w_in,
                         const float* __restrict__ w_o,
                         const float* __restrict__ w1,
                         const float* __restrict__ w2,
                         const float* __restrict__ X) {
    int i = blockIdx.x * 256 + threadIdx.x;
    const int S0 = 4 * 768 * 256, S1 = 4 * 256 * 256;
    const int S2 = 4 * 1024 * 256, S3 = 4 * 256 * 1024, S4 = NWIN * 256;
    if (i < S0) { g_winh[i] = __float2half(w_in[i]); return; }
    i -= S0;
    if (i < S1) { g_woh[i] = __float2half(w_o[i]); return; }
    i -= S1;
    if (i < S2) { g_w1h[i] = __float2half(w1[i]); return; }
    i -= S2;
    if (i < S3) { g_w2h[i] = __float2half(w2[i]); return; }
    i -= S3;
    if (i < S4) { g_xf[i] = __float2half(X[i]); }
}

// pos @ Win^T (fp32, 32x768)
__global__ void pq_kernel(const float* __restrict__ pos,
                          const float* __restrict__ w_in) {
    int idx = blockIdx.x * 256 + threadIdx.x;
    if (idx >= 32 * 768) return;
    int w = idx / 768, c = idx % 768;
    const float* pr = pos + w * 256;
    const float* wr = w_in + (size_t)c * 256;
    float s = 0.f;
#pragma unroll 8
    for (int d = 0; d < 256; d++) s = fmaf(pr[d], wr[d], s);
    g_pq[idx] = s;
}

// ---------------------------------------------------------------------------
// GEMM (NT): C[M,N] = Ah[M,K] @ Bh[N,K]^T + bias[N], fp16 out, opt ReLU.
// CTA 128x128, BK=64, 8 warps (2Mx4N, 64x32), 2-stage cp.async, 2 CTAs/SM.
// ---------------------------------------------------------------------------
template <bool RELU>
__global__ void __launch_bounds__(256, 2) mma_gemm7(
    const __half* __restrict__ Ah, const __half* __restrict__ Bh,
    const float* __restrict__ bias, __half* __restrict__ Ch,
    int K, int N)
{
    extern __shared__ char smem[];
    const uint32_t sb0 = (uint32_t)__cvta_generic_to_shared(smem);

    const int tid  = threadIdx.x;
    const int lane = tid & 31;
    const int wid  = tid >> 5;
    const int bm   = blockIdx.y * 128;
    const int bn   = blockIdx.x * 128;
    const int m0   = (wid >> 2) * 64;
    const int n0   = (wid & 3) * 32;

    const int lrow = lane & 15;
    const int lch  = lane >> 4;
    uint32_t aOff[4], bOff[2];
#pragma unroll
    for (int i = 0; i < 4; i++)
        aOff[i] = (uint32_t)((m0 + i * 16 + lrow) * 144 + lch * 16);
#pragma unroll
    for (int i = 0; i < 2; i++)
        bOff[i] = (uint32_t)((n0 + i * 16 + lrow) * 144 + lch * 16) + (uint32_t)TILEB;

    float c[4][4][4];
#pragma unroll
    for (int i = 0; i < 4; i++)
#pragma unroll
        for (int j = 0; j < 4; j++)
#pragma unroll
            for (int k = 0; k < 4; k++) c[i][j][k] = 0.f;

    auto load_stage = [&](int s, int k0) {
        uint32_t base = sb0 + s * STAGE;
#pragma unroll
        for (int i = 0; i < 8; i++) {
            int cc   = tid + i * 256;
            int isB  = cc >> 10;
            int wi   = cc & 1023;
            int row  = wi >> 3;
            int kc   = wi & 7;
            uint32_t d = base + (uint32_t)(isB * TILEB + row * 144 + kc * 16);
            const __half* src = isB
                ? (Bh + (size_t)(bn + row) * K + k0 + kc * 8)
                : (Ah + (size_t)(bm + row) * K + k0 + kc * 8);
            cp_async16(d, src);
        }
        asm volatile("cp.async.commit_group;" ::: "memory");
    };

    const int ntile = K >> 6;
    load_stage(0, 0);
    for (int it = 0; it < ntile; it++) {
        if (it + 1 < ntile) {
            load_stage((it + 1) & 1, (it + 1) * 64);
            asm volatile("cp.async.wait_group 1;" ::: "memory");
        } else {
            asm volatile("cp.async.wait_group 0;" ::: "memory");
        }
        __syncthreads();

        uint32_t base = sb0 + (it & 1) * STAGE;
#pragma unroll
        for (int ks = 0; ks < 4; ks++) {
            const uint32_t ko = ks * 32;
            uint32_t a[16], bh[8];
            ldsm4(a + 0,  base + aOff[0] + ko);
            ldsm4(a + 4,  base + aOff[1] + ko);
            ldsm4(a + 8,  base + aOff[2] + ko);
            ldsm4(a + 12, base + aOff[3] + ko);
            ldsm4(bh + 0, base + bOff[0] + ko);
            ldsm4(bh + 4, base + bOff[1] + ko);
#pragma unroll
            for (int mi = 0; mi < 4; mi++)
#pragma unroll
                for (int j = 0; j < 4; j++) {
                    int g4 = (j >> 1) * 4, jj = j & 1;
                    mma16816(c[mi][j], a + mi * 4, bh[g4 + jj], bh[g4 + 2 + jj]);
                }
        }
        __syncthreads();
    }

    const int g  = lane >> 2;
    const int t2 = lane & 3;
#pragma unroll
    for (int mi = 0; mi < 4; mi++) {
        int r0 = bm + m0 + mi * 16 + g;
#pragma unroll
        for (int j = 0; j < 4; j++) {
            int col = bn + n0 + j * 8 + t2 * 2;
            float2 bv = *reinterpret_cast<const float2*>(&bias[col]);
            float v0x = c[mi][j][0] + bv.x, v0y = c[mi][j][1] + bv.y;
            float v1x = c[mi][j][2] + bv.x, v1y = c[mi][j][3] + bv.y;
            if (RELU) {
                v0x = fmaxf(v0x, 0.f); v0y = fmaxf(v0y, 0.f);
                v1x = fmaxf(v1x, 0.f); v1y = fmaxf(v1y, 0.f);
            }
            *reinterpret_cast<uint32_t*>(&Ch[(size_t)r0 * N + col]) =
                cvt2h(v0x, v0y);
            *reinterpret_cast<uint32_t*>(&Ch[(size_t)(r0 + 8) * N + col]) =
                cvt2h(v1x, v1y);
        }
    }
}

// ---------------------------------------------------------------------------
// Gather: g_xh fp16 (residual base for layer 0)
// ---------------------------------------------------------------------------
__global__ void gather_kernel(const float* __restrict__ X,
                              const float* __restrict__ pos) {
    int idx = blockIdx.x * 256 + threadIdx.x;
    int d4 = idx & 63;
    int w  = (idx >> 6) & 31;
    int n  = idx >> 11;
    int s  = n & 511;
    int b  = n >> 9;
    int src = s - w; if (src < 0) src = 0;
    float4 xv = reinterpret_cast<const float4*>(X)[(size_t)(b * 512 + src) * 64 + d4];
    float4 pv = reinterpret_cast<const float4*>(pos)[(size_t)w * 64 + d4];
    *reinterpret_cast<uint2*>(&g_xh[(size_t)idx * 4]) =
        make_uint2(cvt2h(xv.x + pv.x, xv.y + pv.y),
                   cvt2h(xv.z + pv.z, xv.w + pv.w));
}

// ---------------------------------------------------------------------------
// Attention core (full-output variant)
// ---------------------------------------------------------------------------
__device__ __forceinline__ void attn_core(
    float (*qs)[36], float (*kT)[36], float (*vs)[36], float (*ps)[36],
    int tid, int bse, int hc, __half* oh)
{
    const int i  = tid >> 2;
    const int jc = tid & 3;

    float q[32];
#pragma unroll
    for (int u = 0; u < 8; u++) {
        float4 t = *reinterpret_cast<const float4*>(&qs[i][u * 4]);
        q[u * 4 + 0] = t.x * SCALE; q[u * 4 + 1] = t.y * SCALE;
        q[u * 4 + 2] = t.z * SCALE; q[u * 4 + 3] = t.w * SCALE;
    }
    float acc[8];
#pragma unroll
    for (int u = 0; u < 8; u++) acc[u] = 0.f;
#pragma unroll
    for (int d = 0; d < 32; d++) {
        float4 k0 = *reinterpret_cast<const float4*>(&kT[d][jc * 8]);
        float4 k1 = *reinterpret_cast<const float4*>(&kT[d][jc * 8 + 4]);
        float qd = q[d];
        acc[0] = fmaf(qd, k0.x, acc[0]); acc[1] = fmaf(qd, k0.y, acc[1]);
        acc[2] = fmaf(qd, k0.z, acc[2]); acc[3] = fmaf(qd, k0.w, acc[3]);
        acc[4] = fmaf(qd, k1.x, acc[4]); acc[5] = fmaf(qd, k1.y, acc[5]);
        acc[6] = fmaf(qd, k1.z, acc[6]); acc[7] = fmaf(qd, k1.w, acc[7]);
    }
    float mx = acc[0];
#pragma unroll
    for (int u = 1; u < 8; u++) mx = fmaxf(mx, acc[u]);
    mx = fmaxf(mx, __shfl_xor_sync(0xffffffffu, mx, 1));
    mx = fmaxf(mx, __shfl_xor_sync(0xffffffffu, mx, 2));
    float sum = 0.f;
#pragma unroll
    for (int u = 0; u < 8; u++) { acc[u] = __expf(acc[u] - mx); sum += acc[u]; }
    sum += __shfl_xor_sync(0xffffffffu, sum, 1);
    sum += __shfl_xor_sync(0xffffffffu, sum, 2);
    float inv = 1.f / sum;
#pragma unroll
    for (int u = 0; u < 8; u++) acc[u] *= inv;
    *reinterpret_cast<float4*>(&ps[i][jc * 8]) =
        make_float4(acc[0], acc[1], acc[2], acc[3]);
    *reinterpret_cast<float4*>(&ps[i][jc * 8 + 4]) =
        make_float4(acc[4], acc[5], acc[6], acc[7]);
    __syncthreads();

    float o[8];
#pragma unroll
    for (int u = 0; u < 8; u++) o[u] = 0.f;
#pragma unroll
    for (int j = 0; j < 32; j++) {
        float pj = ps[i][j];
        float4 v0 = *reinterpret_cast<const float4*>(&vs[j][jc * 8]);
        float4 v1 = *reinterpret_cast<const float4*>(&vs[j][jc * 8 + 4]);
        o[0] = fmaf(pj, v0.x, o[0]); o[1] = fmaf(pj, v0.y, o[1]);
        o[2] = fmaf(pj, v0.z, o[2]); o[3] = fmaf(pj, v0.w, o[3]);
        o[4] = fmaf(pj, v1.x, o[4]); o[5] = fmaf(pj, v1.y, o[5]);
        o[6] = fmaf(pj, v1.z, o[6]); o[7] = fmaf(pj, v1.w, o[7]);
    }
    size_t base = (size_t)(bse + i) * 256 + hc + jc * 8;
    *reinterpret_cast<uint4*>(&oh[base]) =
        make_uint4(cvt2h(o[0], o[1]), cvt2h(o[2], o[3]),
                   cvt2h(o[4], o[5]), cvt2h(o[6], o[7]));
}

// Attention layers 1..2 (full qkv, row stride 768)
__global__ void attn_kernel3(const __half* __restrict__ qkv,
                             __half* __restrict__ oh) {
    __shared__ float qs[32][36];
    __shared__ float kT[32][36];
    __shared__ float vs[32][36];
    __shared__ float ps[32][36];

    const int n   = blockIdx.x >> 3;
    const int h   = blockIdx.x & 7;
    const int tid = threadIdx.x;
    const int bse = n * 32;
    const int hc  = h * 32;

    for (int idx = tid; idx < 384; idx += 128) {
        int c8 = idx & 3;
        int r  = idx >> 2;
        int sect = r >> 5, tok = r & 31;
        uint4 u = *reinterpret_cast<const uint4*>(
            qkv + (size_t)(bse + tok) * 768 + sect * 256 + hc + c8 * 8);
        float f[8];
        unpack8(u, f);
        if (sect == 0) {
#pragma unroll
            for (int i = 0; i < 8; i++) qs[tok][c8 * 8 + i] = f[i];
        } else if (sect == 1) {
#pragma unroll
            for (int i = 0; i < 8; i++) kT[c8 * 8 + i][tok] = f[i];
        } else {
#pragma unroll
            for (int i = 0; i < 8; i++) vs[tok][c8 * 8 + i] = f[i];
        }
    }
    __syncthreads();
    attn_core(qs, kT, vs, ps, tid, bse, hc, oh);
}

// Attention layer 0: qkv[n,w] = T[src(n,w)] + P[w]
__global__ void attn_kernel0(const __half* __restrict__ T,
                             __half* __restrict__ oh) {
    __shared__ float qs[32][36];
    __shared__ float kT[32][36];
    __shared__ float vs[32][36];
    __shared__ float ps[32][36];

    const int n   = blockIdx.x >> 3;
    const int h   = blockIdx.x & 7;
    const int tid = threadIdx.x;
    const int bse = n * 32;
    const int hc  = h * 32;
    const int s   = n & 511;
    const int b   = n >> 9;

    for (int idx = tid; idx < 384; idx += 128) {
        int c8 = idx & 3;
        int r  = idx >> 2;
        int sect = r >> 5, tok = r & 31;
        int src = s - tok; if (src < 0) src = 0;
        size_t off = (size_t)sect * 256 + hc + c8 * 8;
        uint4 u = *reinterpret_cast<const uint4*>(
            T + (size_t)(b * 512 + src) * 768 + off);
        const float* pq = g_pq + (size_t)tok * 768 + off;
        float f[8];
        unpack8(u, f);
#pragma unroll
        for (int i = 0; i < 8; i++) f[i] += pq[i];
        if (sect == 0) {
#pragma unroll
            for (int i = 0; i < 8; i++) qs[tok][c8 * 8 + i] = f[i];
        } else if (sect == 1) {
#pragma unroll
            for (int i = 0; i < 8; i++) kT[c8 * 8 + i][tok] = f[i];
        } else {
#pragma unroll
            for (int i = 0; i < 8; i++) vs[tok][c8 * 8 + i] = f[i];
        }
    }
    __syncthreads();
    attn_core(qs, kT, vs, ps, tid, bse, hc, oh);
}

// Attention layer 3 (minimal): kv = [NTOK x 512] (K cols 0-255, V 256-511),
// q compact [NWIN x 256]; output compact [NWIN x 256].
__global__ void attn_last(const __half* __restrict__ kv,
                          const __half* __restrict__ qc,
                          __half* __restrict__ oh) {
    __shared__ float ks[32][33];   // [tok][d]
    __shared__ float vs[32][33];
    __shared__ float qrow[32];
    __shared__ float pr[32];

    const int n   = blockIdx.x >> 3;
    const int h   = blockIdx.x & 7;
    const int tid = threadIdx.x;   // 128
    const int bse = n * 32;
    const int hc  = h * 32;

    for (int idx = tid; idx < 256; idx += 128) {
        int c8 = idx & 3;
        int r  = idx >> 2;
        int sect = r >> 5, tok = r & 31;
        uint4 u = *reinterpret_cast<const uint4*>(
            kv + (size_t)(bse + tok) * 512 + sect * 256 + hc + c8 * 8);
        float f[8];
        unpack8(u, f);
        float (*dst)[33] = sect ? vs : ks;
#pragma unroll
        for (int i = 0; i < 8; i++) dst[tok][c8 * 8 + i] = f[i];
    }
    if (tid < 32)
        qrow[tid] = __half2float(qc[(size_t)n * 256 + hc + tid]) * SCALE;
    __syncthreads();

    if (tid < 32) {
        float s = 0.f;
#pragma unroll
        for (int d = 0; d < 32; d++) s = fmaf(qrow[d], ks[tid][d], s);
        float mx = s;
#pragma unroll
        for (int o = 16; o > 0; o >>= 1)
            mx = fmaxf(mx, __shfl_xor_sync(0xffffffffu, mx, o));
        float e = __expf(s - mx);
        float sum = e;
#pragma unroll
        for (int o = 16; o > 0; o >>= 1)
            sum += __shfl_xor_sync(0xffffffffu, sum, o);
        pr[tid] = e / sum;
    }
    __syncthreads();

    if (tid < 32) {
        float o = 0.f;
#pragma unroll
        for (int j = 0; j < 32; j++) o = fmaf(pr[j], vs[j][tid], o);
        oh[(size_t)n * 256 + hc + tid] = __float2half(o);
    }
}

// ---------------------------------------------------------------------------
// LayerNorm body
// ---------------------------------------------------------------------------
__device__ __forceinline__ void ln_body(
    const float* vin, const float* gg, const float* bb, int c0, float* r)
{
    float s = 0.f;
#pragma unroll
    for (int j = 0; j < 8; j++) s += vin[j];
#pragma unroll
    for (int o = 16; o > 0; o >>= 1) s += __shfl_xor_sync(0xffffffffu, s, o);
    float mu = s * (1.f / 256.f);
    float s2 = 0.f;
#pragma unroll
    for (int j = 0; j < 8; j++) { float d = vin[j] - mu; s2 += d * d; }
#pragma unroll
    for (int o = 16; o > 0; o >>= 1) s2 += __shfl_xor_sync(0xffffffffu, s2, o);
    float rstd = rsqrtf(s2 * (1.f / 256.f) + EPS);
    float4 g0 = *reinterpret_cast<const float4*>(gg + c0);
    float4 g1 = *reinterpret_cast<const float4*>(gg + c0 + 4);
    float4 b0 = *reinterpret_cast<const float4*>(bb + c0);
    float4 b1 = *reinterpret_cast<const float4*>(bb + c0 + 4);
    r[0] = (vin[0] - mu) * rstd * g0.x + b0.x;
    r[1] = (vin[1] - mu) * rstd * g0.y + b0.y;
    r[2] = (vin[2] - mu) * rstd * g0.z + b0.z;
    r[3] = (vin[3] - mu) * rstd * g0.w + b0.w;
    r[4] = (vin[4] - mu) * rstd * g1.x + b1.x;
    r[5] = (vin[5] - mu) * rstd * g1.y + b1.y;
    r[6] = (vin[6] - mu) * rstd * g1.z + b1.z;
    r[7] = (vin[7] - mu) * rstd * g1.w + b1.w;
}

// Full add+LN on g_xh (fp16 residual, in-place). WRITEQ: also copy w=31 rows
// to g_xq (compact layer-3 Q input).
template <bool WRITEQ>
__global__ void add_ln_kernel(const __half* __restrict__ y,
                              const float* __restrict__ gg,
                              const float* __restrict__ bb) {
    int warp  = threadIdx.x >> 5;
    int lane  = threadIdx.x & 31;
    int token = blockIdx.x * 8 + warp;
    int c0    = lane * 8;
    __half* xr = g_xh + (size_t)token * 256;

    uint4 yu = *reinterpret_cast<const uint4*>(y + (size_t)token * 256 + c0);
    uint4 xu = *reinterpret_cast<const uint4*>(xr + c0);
    float yv[8], xv[8], v[8];
    unpack8(yu, yv);
    unpack8(xu, xv);
#pragma unroll
    for (int j = 0; j < 8; j++) v[j] = xv[j] + yv[j];

    float r[8];
    ln_body(v, gg, bb, c0, r);
    uint4 o = make_uint4(cvt2h(r[0], r[1]), cvt2h(r[2], r[3]),
                         cvt2h(r[4], r[5]), cvt2h(r[6], r[7]));
    *reinterpret_cast<uint4*>(xr + c0) = o;
    if (WRITEQ && (token & 31) == 31)
        *reinterpret_cast<uint4*>(&g_xq[(size_t)(token >> 5) * 256 + c0]) = o;
}

// Compact add+LN (2048 rows): x from xin (fp16, arbitrary row stride), out fp16.
__global__ void add_ln_c(const __half* __restrict__ y,
                         const float* __restrict__ gg,
                         const float* __restrict__ bb,
                         const __half* __restrict__ xin, int xstride,
                         __half* __restrict__ outp) {
    int warp  = threadIdx.x >> 5;
    int lane  = threadIdx.x & 31;
    int token = blockIdx.x * 8 + warp;
    int c0    = lane * 8;

    uint4 yu = *reinterpret_cast<const uint4*>(y + (size_t)token * 256 + c0);
    uint4 xu = *reinterpret_cast<const uint4*>(
        xin + (size_t)token * xstride + c0);
    float yv[8], xv[8], v[8];
    unpack8(yu, yv);
    unpack8(xu, xv);
#pragma unroll
    for (int j = 0; j < 8; j++) v[j] = xv[j] + yv[j];

    float r[8];
    ln_body(v, gg, bb, c0, r);
    *reinterpret_cast<uint4*>(&outp[(size_t)token * 256 + c0]) =
        make_uint4(cvt2h(r[0], r[1]), cvt2h(r[2], r[3]),
                   cvt2h(r[4], r[5]), cvt2h(r[6], r[7]));
}

// ---------------------------------------------------------------------------
// Head: reads compact fp16 g_xc rows.
// ---------------------------------------------------------------------------
__global__ void head_kernel(const float* __restrict__ hw,
                            const float* __restrict__ hb,
                            float* __restrict__ out) {
    __shared__ float hws[32][257];
    __shared__ float xs[8][256];
    int tid = threadIdx.x;
    for (int idx = tid; idx < 32 * 256; idx += 256) {
        int c = idx >> 8, d = idx & 255;
        hws[c][d] = hw[idx];
    }
    int warp = tid >> 5, lane = tid & 31;
    int n = blockIdx.x * 8 + warp;
    {
        uint4 u = *reinterpret_cast<const uint4*>(
            g_xc + (size_t)n * 256 + lane * 8);
        float f[8];
        unpack8(u, f);
#pragma unroll
        for (int j = 0; j < 8; j++) xs[warp][lane * 8 + j] = f[j];
    }
    __syncthreads();

    float accum = hb[lane];
#pragma unroll 8
    for (int d = 0; d < 256; d++) accum = fmaf(xs[warp][d], hws[lane][d], accum);
    out[(size_t)n * 32 + lane] = accum;
}

// ---------------------------------------------------------------------------
// Launch
// ---------------------------------------------------------------------------
extern "C" void kernel_launch(void* const* d_in, const int* in_sizes, int n_in,
                              void* d_out, int out_size) {
    const float* X    = (const float*)d_in[0];
    const float* pos  = (const float*)d_in[3];
    const float* w_in = (const float*)d_in[4];
    const float* b_in = (const float*)d_in[5];
    const float* w_o  = (const float*)d_in[6];
    const float* b_o  = (const float*)d_in[7];
    const float* w1   = (const float*)d_in[8];
    const float* b1   = (const float*)d_in[9];
    const float* w2   = (const float*)d_in[10];
    const float* b2   = (const float*)d_in[11];
    const float* l1g  = (const float*)d_in[12];
    const float* l1b  = (const float*)d_in[13];
    const float* l2g  = (const float*)d_in[14];
    const float* l2b  = (const float*)d_in[15];
    const float* hw   = (const float*)d_in[16];
    const float* hb   = (const float*)d_in[17];
    float* out = (float*)d_out;

    void* p;
    cudaGetSymbolAddress(&p, g_qkv);  __half* qkv = (__half*)p;
    cudaGetSymbolAddress(&p, g_tmp);  __half* tmp = (__half*)p;
    cudaGetSymbolAddress(&p, g_xh);   __half* xh = (__half*)p;
    cudaGetSymbolAddress(&p, g_xq);   __half* xq = (__half*)p;
    cudaGetSymbolAddress(&p, g_qc);   __half* qc = (__half*)p;
    cudaGetSymbolAddress(&p, g_xc);   __half* xc = (__half*)p;
    cudaGetSymbolAddress(&p, g_ah);   __half* ah = (__half*)p;
    cudaGetSymbolAddress(&p, g_fh);   __half* fh = (__half*)p;
    cudaGetSymbolAddress(&p, g_xf);   __half* xf = (__half*)p;
    cudaGetSymbolAddress(&p, g_winh); __half* winh = (__half*)p;
    cudaGetSymbolAddress(&p, g_woh);  __half* woh = (__half*)p;
    cudaGetSymbolAddress(&p, g_w1h);  __half* w1h = (__half*)p;
    cudaGetSymbolAddress(&p, g_w2h);  __half* w2h = (__half*)p;

    cudaFuncSetAttribute(mma_gemm7<false>,
        cudaFuncAttributeMaxDynamicSharedMemorySize, GSMEM);
    cudaFuncSetAttribute(mma_gemm7<true>,
        cudaFuncAttributeMaxDynamicSharedMemorySize, GSMEM);

    const int PREP_N = 4*768*256 + 4*256*256 + 4*1024*256 + 4*256*1024 + NWIN*256;
    prep_all<<<(PREP_N + 255) / 256, 256>>>(w_in, w_o, w1, w2, X);
    pq_kernel<<<(32 * 768 + 255) / 256, 256>>>(pos, w_in);
    gather_kernel<<<NTOK * 64 / 256, 256>>>(X, pos);

    for (int l = 0; l < 4; l++) {
        if (l == 0) {
            mma_gemm7<false><<<dim3(6, 16), 256, GSMEM>>>(
                xf, winh, b_in, qkv, 256, 768);
            attn_kernel0<<<NWIN * 8, 128>>>(qkv, ah);
        } else if (l < 3) {
            mma_gemm7<false><<<dim3(6, 512), 256, GSMEM>>>(
                xh, winh + (size_t)l * 768 * 256,
                b_in + (size_t)l * 768, qkv, 256, 768);
            attn_kernel3<<<NWIN * 8, 128>>>(qkv, ah);
        } else {
            // KV: rows 256..767 of attn_in_w[3]
            mma_gemm7<false><<<dim3(4, 512), 256, GSMEM>>>(
                xh, winh + (size_t)3 * 768 * 256 + 256 * 256,
                b_in + 3 * 768 + 256, qkv, 256, 512);
            // Q compact: 2048 rows
            mma_gemm7<false><<<dim3(2, 16), 256, GSMEM>>>(
                xq, winh + (size_t)3 * 768 * 256,
                b_in + 3 * 768, qc, 256, 256);
            attn_last<<<NWIN * 8, 128>>>(qkv, qc, ah);
        }
        if (l < 3) {
            mma_gemm7<false><<<dim3(2, 512), 256, GSMEM>>>(
                ah, woh + (size_t)l * 256 * 256,
                b_o + (size_t)l * 256, tmp, 256, 256);
            add_ln_kernel<false><<<NTOK / 8, 256>>>(
                tmp, l1g + (size_t)l * 256, l1b + (size_t)l * 256);
            mma_gemm7<true><<<dim3(8, 512), 256, GSMEM>>>(
                xh, w1h + (size_t)l * 1024 * 256,
                b1 + (size_t)l * 1024, fh, 256, 1024);
            mma_gemm7<false><<<dim3(2, 512), 256, GSMEM>>>(
                fh, w2h + (size_t)l * 256 * 1024,
                b2 + (size_t)l * 256, tmp, 1024, 256);
            if (l == 2)
                add_ln_kernel<true><<<NTOK / 8, 256>>>(
                    tmp, l2g + (size_t)l * 256, l2b + (size_t)l * 256);
            else
                add_ln_kernel<false><<<NTOK / 8, 256>>>(
                    tmp, l2g + (size_t)l * 256, l2b + (size_t)l * 256);
        } else {
            mma_gemm7<false><<<dim3(2, 16), 256, GSMEM>>>(
                ah, woh + (size_t)3 * 256 * 256,
                b_o + 3 * 256, tmp, 256, 256);
            // residual base: w=31 rows of xh (= xq content pre-LN? no — xq IS
            // post-LN x2 at w=31, which is exactly the residual base here)
            add_ln_c<<<NWIN / 8, 256>>>(
                tmp, l1g + (size_t)3 * 256, l1b + (size_t)3 * 256,
                xq, 256, xc);
            mma_gemm7<true><<<dim3(8, 16), 256, GSMEM>>>(
                xc, w1h + (size_t)3 * 1024 * 256,
                b1 + (size_t)3 * 1024, fh, 256, 1024);
            mma_gemm7<false><<<dim3(2, 16), 256, GSMEM>>>(
                fh, w2h + (size_t)3 * 256 * 1024,
                b2 + 3 * 256, tmp, 1024, 256);
            add_ln_c<<<NWIN / 8, 256>>>(
                tmp, l2g + (size_t)3 * 256, l2b + (size_t)3 * 256,
                xc, 256, xc);
        }
    }

    head_kernel<<<NWIN / 8, 256>>>(hw, hb, out);
}